// round 9
// baseline (speedup 1.0000x reference)
#include <cuda_runtime.h>

#define BATCH   4
#define SEQ     2048
#define NH      16
#define DK      64
#define D_MODEL 1024

// Scratch (allocation-free rule: __device__ globals)
__device__ __align__(128) float g_vproj[(size_t)BATCH * SEQ * D_MODEL];
__device__ __align__(128) float g_x[(size_t)BATCH * SEQ * D_MODEL];
// packed mask bits: word w covers mask[w*32 .. w*32+31], bit i = (mask != 0)
__device__ __align__(128) unsigned g_maskbits[(size_t)BATCH * SEQ * (SEQ / 32)];

__device__ __forceinline__ float to_tf32(float x) {
    unsigned u;
    asm("cvt.rna.tf32.f32 %0, %1;" : "=r"(u) : "f"(x));
    return __uint_as_float(u);
}

__device__ __forceinline__ void mma8(float* d, const unsigned* a, unsigned b0, unsigned b1) {
    asm volatile(
        "mma.sync.aligned.m16n8k8.row.col.f32.tf32.tf32.f32 "
        "{%0,%1,%2,%3},{%4,%5,%6,%7},{%8,%9},{%0,%1,%2,%3};\n"
        : "+f"(d[0]), "+f"(d[1]), "+f"(d[2]), "+f"(d[3])
        : "r"(a[0]), "r"(a[1]), "r"(a[2]), "r"(a[3]), "r"(b0), "r"(b1));
}

__device__ __forceinline__ void cp16(float* smem_dst, const float* gsrc) {
    unsigned s = (unsigned)__cvta_generic_to_shared(smem_dst);
    asm volatile("cp.async.cg.shared.global [%0], [%1], 16;\n" :: "r"(s), "l"(gsrc));
}
#define CP_COMMIT() asm volatile("cp.async.commit_group;\n" ::: "memory")
#define CP_WAIT2()  asm volatile("cp.async.wait_group 2;\n" ::: "memory")

// ============================================================================
// Pack int32 mask -> bitmask. One warp per 32 consecutive mask elements.
// ============================================================================
__global__ __launch_bounds__(256) void pack_mask(const int* __restrict__ m,
                                                 unsigned* __restrict__ bits,
                                                 int n_words)
{
    int w = blockIdx.x * 8 + (threadIdx.x >> 5);
    int lane = threadIdx.x & 31;
    if (w < n_words) {
        int v = m[(size_t)w * 32 + lane];
        unsigned b = __ballot_sync(0xffffffffu, v != 0);
        if (lane == 0) bits[w] = b;
    }
}

// ============================================================================
// tf32 GEMM: C[M,N] = A[M,K] @ Bw[N,K]^T + bias[N]   (unchanged)
// ============================================================================
__global__ __launch_bounds__(256, 2) void gemm_tf32(
    const float* __restrict__ A, const float* __restrict__ Bw,
    const float* __restrict__ bias, float* __restrict__ C,
    int M, int N, int K, int round_out)
{
    extern __shared__ float dsm[];

    const int tid  = threadIdx.x;
    const int lane = tid & 31, warp = tid >> 5;
    const int group = lane >> 2, t4 = lane & 3;
    const int wm = warp >> 1, wn = warp & 1;
    const int m0 = blockIdx.y * 128, n0 = blockIdx.x * 128;
    const int lr = tid >> 1, lc = (tid & 1) * 16;

    float acc[2][8][4];
#pragma unroll
    for (int i = 0; i < 2; i++)
#pragma unroll
        for (int j = 0; j < 8; j++)
#pragma unroll
            for (int k = 0; k < 4; k++) acc[i][j][k] = 0.f;

    const float* Ap = A + (size_t)(m0 + lr) * K + lc;
    const float* Bp = Bw + (size_t)(n0 + lr) * K + lc;

    float4 pa[4], pb[4];
#pragma unroll
    for (int j = 0; j < 4; j++) {
        pa[j] = *(const float4*)(Ap + 4 * j);
        pb[j] = *(const float4*)(Bp + 4 * j);
    }
    {
        float* sA0 = dsm;
        float* sB0 = dsm + 9216;
#pragma unroll
        for (int j = 0; j < 4; j++) {
            *(float4*)&sA0[lr * 36 + lc + 4 * j] =
                make_float4(to_tf32(pa[j].x), to_tf32(pa[j].y), to_tf32(pa[j].z), to_tf32(pa[j].w));
            *(float4*)&sB0[lr * 36 + lc + 4 * j] =
                make_float4(to_tf32(pb[j].x), to_tf32(pb[j].y), to_tf32(pb[j].z), to_tf32(pb[j].w));
        }
    }
    __syncthreads();

    const int NC = K / 32;
    for (int c = 0; c < NC; c++) {
        if (c + 1 < NC) {
#pragma unroll
            for (int j = 0; j < 4; j++) {
                pa[j] = *(const float4*)(Ap + (c + 1) * 32 + 4 * j);
                pb[j] = *(const float4*)(Bp + (c + 1) * 32 + 4 * j);
            }
        }
        const float* sAc = dsm + (c & 1) * 4608;
        const float* sBc = dsm + 9216 + (c & 1) * 4608;
#pragma unroll
        for (int kk = 0; kk < 32; kk += 8) {
            unsigned a[2][4];
#pragma unroll
            for (int mf = 0; mf < 2; mf++) {
                int r = wm * 32 + mf * 16 + group;
                a[mf][0] = __float_as_uint(sAc[r * 36 + kk + t4]);
                a[mf][1] = __float_as_uint(sAc[(r + 8) * 36 + kk + t4]);
                a[mf][2] = __float_as_uint(sAc[r * 36 + kk + t4 + 4]);
                a[mf][3] = __float_as_uint(sAc[(r + 8) * 36 + kk + t4 + 4]);
            }
#pragma unroll
            for (int nf = 0; nf < 8; nf++) {
                int n = wn * 64 + nf * 8 + group;
                unsigned b0 = __float_as_uint(sBc[n * 36 + kk + t4]);
                unsigned b1 = __float_as_uint(sBc[n * 36 + kk + t4 + 4]);
#pragma unroll
                for (int mf = 0; mf < 2; mf++) mma8(acc[mf][nf], a[mf], b0, b1);
            }
        }
        if (c + 1 < NC) {
            float* sAn = dsm + ((c + 1) & 1) * 4608;
            float* sBn = dsm + 9216 + ((c + 1) & 1) * 4608;
#pragma unroll
            for (int j = 0; j < 4; j++) {
                *(float4*)&sAn[lr * 36 + lc + 4 * j] =
                    make_float4(to_tf32(pa[j].x), to_tf32(pa[j].y), to_tf32(pa[j].z), to_tf32(pa[j].w));
                *(float4*)&sBn[lr * 36 + lc + 4 * j] =
                    make_float4(to_tf32(pb[j].x), to_tf32(pb[j].y), to_tf32(pb[j].z), to_tf32(pb[j].w));
            }
        }
        __syncthreads();
    }

#pragma unroll
    for (int mf = 0; mf < 2; mf++) {
        int r = m0 + wm * 32 + mf * 16 + group;
#pragma unroll
        for (int nf = 0; nf < 8; nf++) {
            int cc = n0 + wn * 64 + nf * 8 + t4 * 2;
            float v00 = acc[mf][nf][0] + bias[cc];
            float v01 = acc[mf][nf][1] + bias[cc + 1];
            float v10 = acc[mf][nf][2] + bias[cc];
            float v11 = acc[mf][nf][3] + bias[cc + 1];
            if (round_out) {
                v00 = to_tf32(v00); v01 = to_tf32(v01);
                v10 = to_tf32(v10); v11 = to_tf32(v11);
            }
            C[(size_t)r * N + cc]           = v00;
            C[(size_t)r * N + cc + 1]       = v01;
            C[(size_t)(r + 8) * N + cc]     = v10;
            C[(size_t)(r + 8) * N + cc + 1] = v11;
        }
    }
}

// ============================================================================
// Fused softmax + attention mix, NO separate convert phase.
// Crossbar was the binding resource (R8 finding): the old pipeline moved
// ~121 KB/chunk through smem. Now: raw W is cp.async'd in; mask+exp+RNA
// happen IN FRAGMENT REGISTERS right before the mma (redundant exp on the 2
// n-warps rides the idle MUFU pipe). Row sums come from an extra mma against
// constant-1.0 B operands (zero smem traffic). 89 KB/chunk remain.
// Pipeline (4 stages, wait_group 2, ONE barrier/iter):
//   iter c: wait_group 2 (chunk c landed) ; barrier (publishes chunk c, and
//   guarantees all warps finished iter c-1 mma so stage (c+3)%4 is free) ;
//   issue chunk c+3 ; commit ; mma+exp on stage c.
//   -> 3 chunks in flight during mma (~150 KB/SM outstanding).
// smem (floats): W stages @0,4608,9216,13824 (128x36 raw); V stages @18432 +
// s*2304 (32x72 raw tf32-prerounded); rowinv @27648. 27776 floats = 111104 B.
// ============================================================================
__global__ __launch_bounds__(256, 2) void mix_softmax(
    const float* __restrict__ W)
{
    extern __shared__ float dsm[];

    const int tid  = threadIdx.x;
    const int lane = tid & 31, warp = tid >> 5;
    const int group = lane >> 2, t4 = lane & 3;
    const int wm = warp >> 1, wn = warp & 1;
    const int bh = blockIdx.y, b = bh >> 4, h = bh & 15;
    const int q0 = blockIdx.x * 128;

    const int rw = tid >> 1, cw = (tid & 1) * 16;   // W loader: 2 thr/row, 16 cols each
    const int rv = tid >> 3, cv = (tid & 7) * 8;    // V loader: 8 thr/row, 8 cols each

    const float* gW = W + ((size_t)bh * SEQ + q0 + rw) * SEQ + cw;
    const float* gV = g_vproj + (size_t)b * SEQ * D_MODEL + (size_t)rv * D_MODEL + h * DK + cv;

    float* const sW0 = dsm;                 // 4 x 4608 (raw W)
    float* const sV0 = dsm + 18432;         // 4 x 2304 (raw tf32 V)

    // mask word pointers for this thread's 4 fragment rows:
    // rows wm*32+group + {0,8,16,24}  (mf0: +0,+8 ; mf1: +16,+24)
    const int r0 = wm * 32 + group;
    const unsigned* MbR0 = g_maskbits + ((size_t)b * SEQ + q0 + r0)      * (SEQ / 32);
    const unsigned* MbR1 = g_maskbits + ((size_t)b * SEQ + q0 + r0 + 8)  * (SEQ / 32);
    const unsigned* MbR2 = g_maskbits + ((size_t)b * SEQ + q0 + r0 + 16) * (SEQ / 32);
    const unsigned* MbR3 = g_maskbits + ((size_t)b * SEQ + q0 + r0 + 24) * (SEQ / 32);

    float acc[2][4][4];
#pragma unroll
    for (int i = 0; i < 2; i++)
#pragma unroll
        for (int j = 0; j < 4; j++)
#pragma unroll
            for (int k = 0; k < 4; k++) acc[i][j][k] = 0.f;
    float acc1[2][4];   // rowsum accumulators (meaningful on wn==0 warps)
#pragma unroll
    for (int i = 0; i < 2; i++)
#pragma unroll
        for (int k = 0; k < 4; k++) acc1[i][k] = 0.f;

    const unsigned ONE = 0x3f800000u;   // 1.0f, exact in tf32

    // ---- prologue: issue chunks 0,1,2 (3 commit groups) ----
#pragma unroll
    for (int s = 0; s < 3; s++) {
        float* sWs = sW0 + s * 4608;
        float* sVs = sV0 + s * 2304;
        const float* srcW = gW + (size_t)s * 32;
        const float* srcV = gV + (size_t)s * 32 * D_MODEL;
#pragma unroll
        for (int j = 0; j < 4; j++) cp16(&sWs[rw * 36 + cw + 4 * j], srcW + 4 * j);
        cp16(&sVs[rv * 72 + cv], srcV);
        cp16(&sVs[rv * 72 + cv + 4], srcV + 4);
        CP_COMMIT();
    }

    unsigned m0 = MbR0[0], m1 = MbR1[0], m2 = MbR2[0], m3 = MbR3[0];

    // ---- main loop ----
    for (int c = 0; c < 64; c++) {
        CP_WAIT2();        // chunk c fully landed (<=2 groups pending)
        __syncthreads();   // publish chunk c to all warps; all warps are past
                           // iter c-1's mma, so stage (c+3)%4 is reusable

        // issue chunk c+3 -> stage (c+3)%4
        if (c + 3 < 64) {
            const int s = (c + 3) & 3;
            float* sWs = sW0 + s * 4608;
            float* sVs = sV0 + s * 2304;
            const float* srcW = gW + (size_t)(c + 3) * 32;
            const float* srcV = gV + (size_t)(c + 3) * 32 * D_MODEL;
#pragma unroll
            for (int j = 0; j < 4; j++) cp16(&sWs[rw * 36 + cw + 4 * j], srcW + 4 * j);
            cp16(&sVs[rv * 72 + cv], srcV);
            cp16(&sVs[rv * 72 + cv + 4], srcV + 4);
        }
        CP_COMMIT();   // empty group at tail keeps wait_group counting aligned

        // prefetch mask words for chunk c+1 (LDG latency hides behind mma)
        unsigned n0_ = 0, n1_ = 0, n2_ = 0, n3_ = 0;
        if (c + 1 < 64) {
            n0_ = MbR0[c + 1]; n1_ = MbR1[c + 1];
            n2_ = MbR2[c + 1]; n3_ = MbR3[c + 1];
        }

        // mma on stage c, exp fused into fragment load
        {
            const float* sWb = sW0 + (c & 3) * 4608;
            const float* sVb = sV0 + (c & 3) * 2304;
#pragma unroll
            for (int kk = 0; kk < 32; kk += 8) {
                unsigned a[2][4];
#pragma unroll
                for (int mf = 0; mf < 2; mf++) {
                    const int r = wm * 32 + mf * 16 + group;
                    float x0 = sWb[r * 36 + kk + t4];
                    float x1 = sWb[(r + 8) * 36 + kk + t4];
                    float x2 = sWb[r * 36 + kk + t4 + 4];
                    float x3 = sWb[(r + 8) * 36 + kk + t4 + 4];
                    const unsigned ma = mf ? m2 : m0;   // word for row r
                    const unsigned mb = mf ? m3 : m1;   // word for row r+8
                    float e0 = ((ma >> (kk + t4)) & 1u)     ? __expf(x0) : 0.f;
                    float e1 = ((mb >> (kk + t4)) & 1u)     ? __expf(x1) : 0.f;
                    float e2 = ((ma >> (kk + t4 + 4)) & 1u) ? __expf(x2) : 0.f;
                    float e3 = ((mb >> (kk + t4 + 4)) & 1u) ? __expf(x3) : 0.f;
                    a[mf][0] = __float_as_uint(to_tf32(e0));
                    a[mf][1] = __float_as_uint(to_tf32(e1));
                    a[mf][2] = __float_as_uint(to_tf32(e2));
                    a[mf][3] = __float_as_uint(to_tf32(e3));
                    if (wn == 0) mma8(acc1[mf], a[mf], ONE, ONE);  // rowsum
                }
#pragma unroll
                for (int nf = 0; nf < 4; nf++) {
                    int n = wn * 32 + nf * 8 + group;
                    unsigned b0 = __float_as_uint(sVb[(kk + t4) * 72 + n]);
                    unsigned b1 = __float_as_uint(sVb[(kk + t4 + 4) * 72 + n]);
#pragma unroll
                    for (int mf = 0; mf < 2; mf++) mma8(acc[mf][nf], a[mf], b0, b1);
                }
            }
        }
        m0 = n0_; m1 = n1_; m2 = n2_; m3 = n3_;
    }

    // rowsum (fp32, from the SAME rounded P used in the numerator) -> 1/sum
    if (wn == 0 && t4 == 0) {
#pragma unroll
        for (int mf = 0; mf < 2; mf++) {
            int r = wm * 32 + mf * 16 + group;
            dsm[27648 + r]     = 1.0f / acc1[mf][0];
            dsm[27648 + r + 8] = 1.0f / acc1[mf][2];
        }
    }
    __syncthreads();

    // epilogue: scale by 1/rowsum, write x[b, q, h*64 + d]
    {
        float* Xb = g_x + (size_t)b * SEQ * D_MODEL + h * DK;
#pragma unroll
        for (int mf = 0; mf < 2; mf++) {
            int rr = wm * 32 + mf * 16 + group;
            float s0 = dsm[27648 + rr];
            float s1 = dsm[27648 + rr + 8];
            int qr = q0 + rr;
#pragma unroll
            for (int nf = 0; nf < 4; nf++) {
                int n = wn * 32 + nf * 8 + t4 * 2;
                Xb[(size_t)qr * D_MODEL + n]           = acc[mf][nf][0] * s0;
                Xb[(size_t)qr * D_MODEL + n + 1]       = acc[mf][nf][1] * s0;
                Xb[(size_t)(qr + 8) * D_MODEL + n]     = acc[mf][nf][2] * s1;
                Xb[(size_t)(qr + 8) * D_MODEL + n + 1] = acc[mf][nf][3] * s1;
            }
        }
    }
}

// ============================================================================
// Launch: pack mask -> V-proj GEMM (tf32-rounded out) -> mix -> O-proj GEMM
// Inputs: 0 query(unused) 1 key(unused) 2 value 3 weight 4 mask(int32)
//         5 V_w 6 V_b 7 O_w 8 O_b
// ============================================================================
extern "C" void kernel_launch(void* const* d_in, const int* in_sizes, int n_in,
                              void* d_out, int out_size)
{
    const float* value  = (const float*)d_in[2];
    const float* weight = (const float*)d_in[3];
    const int*   mask   = (const int*)d_in[4];
    const float* V_w    = (const float*)d_in[5];
    const float* V_b    = (const float*)d_in[6];
    const float* O_w    = (const float*)d_in[7];
    const float* O_b    = (const float*)d_in[8];
    float* out          = (float*)d_out;

    float *vp, *xp;
    unsigned* mb;
    cudaGetSymbolAddress((void**)&vp, g_vproj);
    cudaGetSymbolAddress((void**)&xp, g_x);
    cudaGetSymbolAddress((void**)&mb, g_maskbits);

    cudaFuncSetAttribute(gemm_tf32, cudaFuncAttributeMaxDynamicSharedMemorySize, 73728);
    cudaFuncSetAttribute(mix_softmax, cudaFuncAttributeMaxDynamicSharedMemorySize, 111104);

    const int n_words = BATCH * SEQ * (SEQ / 32);

    dim3 blk(256);
    dim3 g0((n_words + 7) / 8);
    dim3 g1(D_MODEL / 128, (BATCH * SEQ) / 128);   // (8, 64)
    dim3 g2(SEQ / 128, BATCH * NH);                // (16, 64)

    pack_mask<<<g0, blk>>>(mask, mb, n_words);
    gemm_tf32<<<g1, blk, 73728>>>(value, V_w, V_b, vp, BATCH * SEQ, D_MODEL, D_MODEL, 1);
    mix_softmax<<<g2, blk, 111104>>>(weight);
    gemm_tf32<<<g1, blk, 73728>>>(xp, O_w, O_b, out, BATCH * SEQ, D_MODEL, D_MODEL, 0);
}

// round 12
// speedup vs baseline: 1.0127x; 1.0127x over previous
#include <cuda_runtime.h>
#include <cuda_fp16.h>

#define BATCH   4
#define SEQ     2048
#define NH      16
#define DK      64
#define D_MODEL 1024

// Scratch (allocation-free rule: __device__ globals)
__device__ __align__(128) __half g_vprojh[(size_t)BATCH * SEQ * D_MODEL];     // [b][s][h*64+d]
__device__ __align__(128) __half g_vprojTh[(size_t)BATCH * NH * DK * SEQ];    // [bh][d][s]
__device__ __align__(128) float  g_x[(size_t)BATCH * SEQ * D_MODEL];
__device__ __align__(128) unsigned g_maskbits[(size_t)BATCH * SEQ * (SEQ / 32)];

__device__ __forceinline__ unsigned pack2h(float x, float y) {
    __half2 h = __floats2half2_rn(x, y);
    return *(unsigned*)&h;
}

__device__ __forceinline__ void mma16(float* d, const unsigned* a, unsigned b0, unsigned b1) {
    asm volatile(
        "mma.sync.aligned.m16n8k16.row.col.f32.f16.f16.f32 "
        "{%0,%1,%2,%3},{%4,%5,%6,%7},{%8,%9},{%0,%1,%2,%3};\n"
        : "+f"(d[0]), "+f"(d[1]), "+f"(d[2]), "+f"(d[3])
        : "r"(a[0]), "r"(a[1]), "r"(a[2]), "r"(a[3]), "r"(b0), "r"(b1));
}

__device__ __forceinline__ void cp16s(unsigned saddr, const void* g) {
    asm volatile("cp.async.cg.shared.global [%0], [%1], 16;" :: "r"(saddr), "l"(g));
}
#define CP_COMMIT() asm volatile("cp.async.commit_group;" ::: "memory")
#define CP_WAIT0()  asm volatile("cp.async.wait_group 0;" ::: "memory")

__device__ __forceinline__ unsigned smem_u32(const void* p) {
    unsigned a;
    asm("{ .reg .u64 t; cvta.to.shared.u64 t, %1; cvt.u32.u64 %0, t; }" : "=r"(a) : "l"(p));
    return a;
}

// ============================================================================
// Pack int32 mask -> bitmask.
// ============================================================================
__global__ __launch_bounds__(256) void pack_mask(const int* __restrict__ m,
                                                 unsigned* __restrict__ bits, int n_words)
{
    int w = blockIdx.x * 8 + (threadIdx.x >> 5);
    int lane = threadIdx.x & 31;
    if (w < n_words) {
        int v = m[(size_t)w * 32 + lane];
        unsigned b = __ballot_sync(0xffffffffu, v != 0);
        if (lane == 0) bits[w] = b;
    }
}

// ============================================================================
// fp16 GEMM: C[M,N] = A[M,K] @ Bw[N,K]^T + bias[N]
// A, Bw fp32 in gmem, converted to fp16 (RN) at smem store. acc fp32.
// BM=128, BN=128, BK=32, 256 threads = 8 warps (4m x 2n), warp tile 32x64.
// mma m16n8k16: 2 k-steps/chunk, half the fragment LDS bytes of the tf32 path.
// smem halves, pitch 40 (80 B: 16B-aligned, conflict-free fragment banks):
//   sA stages @0,@5120 ; sB stages @10240,@15360. 20480 halves = 40960 B.
// out_half: write __half (for the V projection feeding the fp16 mix).
// ============================================================================
__global__ __launch_bounds__(256, 2) void gemm_fp16(
    const float* __restrict__ A, const float* __restrict__ Bw,
    const float* __restrict__ bias, void* __restrict__ Cout,
    int M, int N, int K, int out_half)
{
    extern __shared__ __half hsm[];

    const int tid  = threadIdx.x;
    const int lane = tid & 31, warp = tid >> 5;
    const int g    = lane >> 2, t4 = lane & 3;
    const int wm = warp >> 1, wn = warp & 1;
    const int m0 = blockIdx.y * 128, n0 = blockIdx.x * 128;
    const int lr = tid >> 1, lc = (tid & 1) * 16;

    float acc[2][8][4];
#pragma unroll
    for (int i = 0; i < 2; i++)
#pragma unroll
        for (int j = 0; j < 8; j++)
#pragma unroll
            for (int k = 0; k < 4; k++) acc[i][j][k] = 0.f;

    const float* Ap = A + (size_t)(m0 + lr) * K + lc;
    const float* Bp = Bw + (size_t)(n0 + lr) * K + lc;

    float4 pa[4], pb[4];
#pragma unroll
    for (int j = 0; j < 4; j++) {
        pa[j] = *(const float4*)(Ap + 4 * j);
        pb[j] = *(const float4*)(Bp + 4 * j);
    }
    {
        __half* sA = hsm;
        __half* sB = hsm + 10240;
        *(uint4*)(sA + lr * 40 + lc) = make_uint4(
            pack2h(pa[0].x, pa[0].y), pack2h(pa[0].z, pa[0].w),
            pack2h(pa[1].x, pa[1].y), pack2h(pa[1].z, pa[1].w));
        *(uint4*)(sA + lr * 40 + lc + 8) = make_uint4(
            pack2h(pa[2].x, pa[2].y), pack2h(pa[2].z, pa[2].w),
            pack2h(pa[3].x, pa[3].y), pack2h(pa[3].z, pa[3].w));
        *(uint4*)(sB + lr * 40 + lc) = make_uint4(
            pack2h(pb[0].x, pb[0].y), pack2h(pb[0].z, pb[0].w),
            pack2h(pb[1].x, pb[1].y), pack2h(pb[1].z, pb[1].w));
        *(uint4*)(sB + lr * 40 + lc + 8) = make_uint4(
            pack2h(pb[2].x, pb[2].y), pack2h(pb[2].z, pb[2].w),
            pack2h(pb[3].x, pb[3].y), pack2h(pb[3].z, pb[3].w));
    }
    __syncthreads();

    const int NC = K / 32;
    for (int c = 0; c < NC; c++) {
        if (c + 1 < NC) {
#pragma unroll
            for (int j = 0; j < 4; j++) {
                pa[j] = *(const float4*)(Ap + (c + 1) * 32 + 4 * j);
                pb[j] = *(const float4*)(Bp + (c + 1) * 32 + 4 * j);
            }
        }
        const __half* sAc = hsm + (c & 1) * 5120;
        const __half* sBc = hsm + 10240 + (c & 1) * 5120;
#pragma unroll
        for (int ks = 0; ks < 32; ks += 16) {
            unsigned a[2][4];
#pragma unroll
            for (int mf = 0; mf < 2; mf++) {
                int r = wm * 32 + mf * 16 + g;
                a[mf][0] = *(const unsigned*)(sAc + r * 40 + ks + 2 * t4);
                a[mf][1] = *(const unsigned*)(sAc + (r + 8) * 40 + ks + 2 * t4);
                a[mf][2] = *(const unsigned*)(sAc + r * 40 + ks + 2 * t4 + 8);
                a[mf][3] = *(const unsigned*)(sAc + (r + 8) * 40 + ks + 2 * t4 + 8);
            }
#pragma unroll
            for (int nf = 0; nf < 8; nf++) {
                int n = wn * 64 + nf * 8 + g;
                unsigned b0 = *(const unsigned*)(sBc + n * 40 + ks + 2 * t4);
                unsigned b1 = *(const unsigned*)(sBc + n * 40 + ks + 2 * t4 + 8);
#pragma unroll
                for (int mf = 0; mf < 2; mf++) mma16(acc[mf][nf], a[mf], b0, b1);
            }
        }
        if (c + 1 < NC) {
            __half* sAn = hsm + ((c + 1) & 1) * 5120;
            __half* sBn = hsm + 10240 + ((c + 1) & 1) * 5120;
            *(uint4*)(sAn + lr * 40 + lc) = make_uint4(
                pack2h(pa[0].x, pa[0].y), pack2h(pa[0].z, pa[0].w),
                pack2h(pa[1].x, pa[1].y), pack2h(pa[1].z, pa[1].w));
            *(uint4*)(sAn + lr * 40 + lc + 8) = make_uint4(
                pack2h(pa[2].x, pa[2].y), pack2h(pa[2].z, pa[2].w),
                pack2h(pa[3].x, pa[3].y), pack2h(pa[3].z, pa[3].w));
            *(uint4*)(sBn + lr * 40 + lc) = make_uint4(
                pack2h(pb[0].x, pb[0].y), pack2h(pb[0].z, pb[0].w),
                pack2h(pb[1].x, pb[1].y), pack2h(pb[1].z, pb[1].w));
            *(uint4*)(sBn + lr * 40 + lc + 8) = make_uint4(
                pack2h(pb[2].x, pb[2].y), pack2h(pb[2].z, pb[2].w),
                pack2h(pb[3].x, pb[3].y), pack2h(pb[3].z, pb[3].w));
        }
        __syncthreads();
    }

#pragma unroll
    for (int mf = 0; mf < 2; mf++) {
        int r = m0 + wm * 32 + mf * 16 + g;
#pragma unroll
        for (int nf = 0; nf < 8; nf++) {
            int cc = n0 + wn * 64 + nf * 8 + t4 * 2;
            float v00 = acc[mf][nf][0] + bias[cc];
            float v01 = acc[mf][nf][1] + bias[cc + 1];
            float v10 = acc[mf][nf][2] + bias[cc];
            float v11 = acc[mf][nf][3] + bias[cc + 1];
            if (out_half) {
                __half* Ch = (__half*)Cout;
                *(__half2*)(Ch + (size_t)r * N + cc)       = __floats2half2_rn(v00, v01);
                *(__half2*)(Ch + (size_t)(r + 8) * N + cc) = __floats2half2_rn(v10, v11);
            } else {
                float* C = (float*)Cout;
                C[(size_t)r * N + cc]           = v00;
                C[(size_t)r * N + cc + 1]       = v01;
                C[(size_t)(r + 8) * N + cc]     = v10;
                C[(size_t)(r + 8) * N + cc + 1] = v11;
            }
        }
    }
}

// ============================================================================
// Transpose v (half, bits preserved): g_vprojh [b][s][h*64+d] -> g_vprojTh
// [bh][d][s]. Block = 64s x 64d tile of one (b,h). grid (SEQ/64, B*H).
// ============================================================================
__global__ __launch_bounds__(256) void transpose_v()
{
    __shared__ __half t[64][72];
    const int bh = blockIdx.y, b = bh >> 4, h = bh & 15;
    const int s0 = blockIdx.x * 64;
    const int r = threadIdx.x >> 2, c0 = (threadIdx.x & 3) * 16;

    const __half* src = g_vprojh + ((size_t)b * SEQ + s0 + r) * D_MODEL + h * DK + c0;
    *(uint4*)&t[r][c0]     = *(const uint4*)(src);
    *(uint4*)&t[r][c0 + 8] = *(const uint4*)(src + 8);
    __syncthreads();

    // here r = d index, c0 = s offset
    __half* dst = g_vprojTh + ((size_t)bh * DK + r) * SEQ + s0 + c0;
    unsigned q[8];
#pragma unroll
    for (int j = 0; j < 8; j++) {
        __half2 p = __halves2half2(t[c0 + 2 * j][r], t[c0 + 2 * j + 1][r]);
        q[j] = *(unsigned*)&p;
    }
    *(uint4*)(dst)     = make_uint4(q[0], q[1], q[2], q[3]);
    *(uint4*)(dst + 8) = make_uint4(q[4], q[5], q[6], q[7]);
}

// ============================================================================
// Fused softmax + attention mix, fp16 mma (R5 skeleton, halved bytes).
// No-max softmax: fp32 logits can't overflow exp; masked entries -> e=0.
// One block = 128 q-rows of one (b,h); 64 k-chunks of 32.
// Per iter c: cp.async V(c+1); mma (m16n8k16) on stage c&1; produce P(c+1)
//   from prefetched W regs (fp32 exp -> half2 STS); LDG W(c+2); wait; barrier.
// Crossbar/chunk ~45 KB (vs 89 tf32); smem 31 KB -> 3 CTAs/SM (48 KB W in
// flight). Rowsum in fp32 producer regs (+shfl), numerator uses half P/V.
// smem halves: P stages @0,@5120 (128x40); V stages @10240,@12800 (64x40);
// rowinv (float[128]) @15360h = byte 30720. Total 31232 B.
// ============================================================================
#define MIX_SMEM_REQ 31232

__global__ __launch_bounds__(256, 3) void mix_fp16(const float* __restrict__ W)
{
    extern __shared__ __half hsm[];
    float* rinv = (float*)(hsm + 15360);

    const int tid  = threadIdx.x;
    const int lane = tid & 31, warp = tid >> 5;
    const int g    = lane >> 2, t4 = lane & 3;
    const int wm = warp >> 1, wn = warp & 1;
    const int bh = blockIdx.y, b = bh >> 4, h = bh & 15;
    const int q0 = blockIdx.x * 128;

    // W producer: 2 thr/row, 16 cols each
    const int rw = tid >> 1, cw = (tid & 1) * 16;
    const float*    gW = W + ((size_t)bh * SEQ + q0 + rw) * SEQ + cw;
    const unsigned* Mb = g_maskbits + ((size_t)b * SEQ + q0 + rw) * (SEQ / 32);

    // V producer: 1 granule (16 B = 8 halves) per thread: row vr, col vg*8
    const int vr = tid >> 2, vg = tid & 3;
    const __half* gV = g_vprojTh + (size_t)bh * DK * SEQ + (size_t)vr * SEQ + vg * 8;
    const unsigned sV0a = smem_u32(hsm + 10240) + (unsigned)(vr * 40 + vg * 8) * 2;

    float acc[2][4][4];
#pragma unroll
    for (int i = 0; i < 2; i++)
#pragma unroll
        for (int j = 0; j < 4; j++)
#pragma unroll
            for (int k = 0; k < 4; k++) acc[i][j][k] = 0.f;

    float lsum = 0.f;
    float4 w[4];
    unsigned mb;

    // ---- prologue ----
#pragma unroll
    for (int j = 0; j < 4; j++) w[j] = __ldcs((const float4*)(gW + 4 * j));
    mb = Mb[0];
    cp16s(sV0a, gV);                      // V chunk 0 -> stage 0
    CP_COMMIT();
    {   // produce P0 -> stage 0
        __half* sP = hsm;
#pragma unroll
        for (int j = 0; j < 4; j++) {
            const int base = cw + 4 * j;
            float e0 = ((mb >> (base + 0)) & 1u) ? __expf(w[j].x) : 0.f;
            float e1 = ((mb >> (base + 1)) & 1u) ? __expf(w[j].y) : 0.f;
            float e2 = ((mb >> (base + 2)) & 1u) ? __expf(w[j].z) : 0.f;
            float e3 = ((mb >> (base + 3)) & 1u) ? __expf(w[j].w) : 0.f;
            lsum += (e0 + e1) + (e2 + e3);
            *(uint2*)(sP + rw * 40 + base) = make_uint2(pack2h(e0, e1), pack2h(e2, e3));
        }
    }
#pragma unroll
    for (int j = 0; j < 4; j++) w[j] = __ldcs((const float4*)(gW + 32 + 4 * j));
    mb = Mb[1];
    CP_WAIT0();
    __syncthreads();

    // ---- main loop ----
    for (int c = 0; c < 64; c++) {
        // V chunk c+1 -> stage (c+1)&1 (that stage's mma finished last iter)
        if (c + 1 < 64) {
            cp16s(sV0a + ((c + 1) & 1) * 5120, gV + (size_t)(c + 1) * 32);
            CP_COMMIT();
        }

        // mma on stage c&1
        {
            const __half* sPb = hsm + (c & 1) * 5120;
            const __half* sVb = hsm + 10240 + (c & 1) * 2560;
#pragma unroll
            for (int ks = 0; ks < 32; ks += 16) {
                unsigned a[2][4];
#pragma unroll
                for (int mf = 0; mf < 2; mf++) {
                    int r = wm * 32 + mf * 16 + g;
                    a[mf][0] = *(const unsigned*)(sPb + r * 40 + ks + 2 * t4);
                    a[mf][1] = *(const unsigned*)(sPb + (r + 8) * 40 + ks + 2 * t4);
                    a[mf][2] = *(const unsigned*)(sPb + r * 40 + ks + 2 * t4 + 8);
                    a[mf][3] = *(const unsigned*)(sPb + (r + 8) * 40 + ks + 2 * t4 + 8);
                }
#pragma unroll
                for (int nf = 0; nf < 4; nf++) {
                    int n = wn * 32 + nf * 8 + g;
                    unsigned b0 = *(const unsigned*)(sVb + n * 40 + ks + 2 * t4);
                    unsigned b1 = *(const unsigned*)(sVb + n * 40 + ks + 2 * t4 + 8);
#pragma unroll
                    for (int mf = 0; mf < 2; mf++) mma16(acc[mf][nf], a[mf], b0, b1);
                }
            }
        }

        // produce P(c+1) -> stage (c+1)&1 from regs w (= chunk c+1)
        if (c + 1 < 64) {
            __half* sP = hsm + ((c + 1) & 1) * 5120;
#pragma unroll
            for (int j = 0; j < 4; j++) {
                const int base = cw + 4 * j;
                float e0 = ((mb >> (base + 0)) & 1u) ? __expf(w[j].x) : 0.f;
                float e1 = ((mb >> (base + 1)) & 1u) ? __expf(w[j].y) : 0.f;
                float e2 = ((mb >> (base + 2)) & 1u) ? __expf(w[j].z) : 0.f;
                float e3 = ((mb >> (base + 3)) & 1u) ? __expf(w[j].w) : 0.f;
                lsum += (e0 + e1) + (e2 + e3);
                *(uint2*)(sP + rw * 40 + base) = make_uint2(pack2h(e0, e1), pack2h(e2, e3));
            }
            // LDG W chunk c+2 (lands during next iter's mma)
            if (c + 2 < 64) {
                const float* gWn = gW + (size_t)(c + 2) * 32;
#pragma unroll
                for (int j = 0; j < 4; j++) w[j] = __ldcs((const float4*)(gWn + 4 * j));
                mb = Mb[c + 2];
            }
            CP_WAIT0();
        }
        __syncthreads();
    }

    // row sums: 2 threads per row, then invert
    {
        float tot = lsum + __shfl_xor_sync(0xffffffffu, lsum, 1);
        if (!(tid & 1)) rinv[rw] = 1.0f / tot;
    }
    __syncthreads();

    // epilogue: scale by 1/rowsum, write x[b, q, h*64 + d] (fp32)
    {
        float* Xb = g_x + (size_t)b * SEQ * D_MODEL + h * DK;
#pragma unroll
        for (int mf = 0; mf < 2; mf++) {
            int rr = wm * 32 + mf * 16 + g;
            float s0 = rinv[rr];
            float s1 = rinv[rr + 8];
            int qr = q0 + rr;
#pragma unroll
            for (int nf = 0; nf < 4; nf++) {
                int n = wn * 32 + nf * 8 + t4 * 2;
                Xb[(size_t)qr * D_MODEL + n]           = acc[mf][nf][0] * s0;
                Xb[(size_t)qr * D_MODEL + n + 1]       = acc[mf][nf][1] * s0;
                Xb[(size_t)(qr + 8) * D_MODEL + n]     = acc[mf][nf][2] * s1;
                Xb[(size_t)(qr + 8) * D_MODEL + n + 1] = acc[mf][nf][3] * s1;
            }
        }
    }
}

// ============================================================================
// Launch: pack mask -> V-proj GEMM (half out) -> transpose -> mix -> O-proj
// Inputs: 0 query(unused) 1 key(unused) 2 value 3 weight 4 mask(int32)
//         5 V_w 6 V_b 7 O_w 8 O_b
// ============================================================================
extern "C" void kernel_launch(void* const* d_in, const int* in_sizes, int n_in,
                              void* d_out, int out_size)
{
    const float* value  = (const float*)d_in[2];
    const float* weight = (const float*)d_in[3];
    const int*   mask   = (const int*)d_in[4];
    const float* V_w    = (const float*)d_in[5];
    const float* V_b    = (const float*)d_in[6];
    const float* O_w    = (const float*)d_in[7];
    const float* O_b    = (const float*)d_in[8];
    float* out          = (float*)d_out;

    __half* vph;
    float* xp;
    unsigned* mb;
    cudaGetSymbolAddress((void**)&vph, g_vprojh);
    cudaGetSymbolAddress((void**)&xp, g_x);
    cudaGetSymbolAddress((void**)&mb, g_maskbits);

    cudaFuncSetAttribute(gemm_fp16, cudaFuncAttributeMaxDynamicSharedMemorySize, 40960);
    cudaFuncSetAttribute(mix_fp16, cudaFuncAttributeMaxDynamicSharedMemorySize, MIX_SMEM_REQ);

    const int n_words = BATCH * SEQ * (SEQ / 32);

    dim3 blk(256);
    dim3 g0((n_words + 7) / 8);
    dim3 g1(D_MODEL / 128, (BATCH * SEQ) / 128);   // (8, 64)
    dim3 gt(SEQ / 64, BATCH * NH);                 // (32, 64)
    dim3 g2(SEQ / 128, BATCH * NH);                // (16, 64)

    pack_mask<<<g0, blk>>>(mask, mb, n_words);
    gemm_fp16<<<g1, blk, 40960>>>(value, V_w, V_b, vph, BATCH * SEQ, D_MODEL, D_MODEL, 1);
    transpose_v<<<gt, blk>>>();
    mix_fp16<<<g2, blk, MIX_SMEM_REQ>>>(weight);
    gemm_fp16<<<g1, blk, 40960>>>(xp, O_w, O_b, out, BATCH * SEQ, D_MODEL, D_MODEL, 0);
}

// round 13
// speedup vs baseline: 1.4405x; 1.4224x over previous
#include <cuda_runtime.h>
#include <cuda_fp16.h>

#define BATCH   4
#define SEQ     2048
#define NH      16
#define DK      64
#define D_MODEL 1024

// Scratch (allocation-free rule: __device__ globals)
__device__ __align__(128) float  g_vproj[(size_t)BATCH * SEQ * D_MODEL];      // fp32 [b][s][h*64+d]
__device__ __align__(128) __half g_vprojTh[(size_t)BATCH * NH * DK * SEQ];    // half [bh][d][s]
__device__ __align__(128) float  g_x[(size_t)BATCH * SEQ * D_MODEL];
__device__ __align__(128) unsigned g_maskbits[(size_t)BATCH * SEQ * (SEQ / 32)];

__device__ __forceinline__ float to_tf32(float x) {
    unsigned u;
    asm("cvt.rna.tf32.f32 %0, %1;" : "=r"(u) : "f"(x));
    return __uint_as_float(u);
}

__device__ __forceinline__ unsigned pack2h(float x, float y) {
    __half2 h = __floats2half2_rn(x, y);
    return *(unsigned*)&h;
}

__device__ __forceinline__ void mma8(float* d, const unsigned* a, unsigned b0, unsigned b1) {
    asm volatile(
        "mma.sync.aligned.m16n8k8.row.col.f32.tf32.tf32.f32 "
        "{%0,%1,%2,%3},{%4,%5,%6,%7},{%8,%9},{%0,%1,%2,%3};\n"
        : "+f"(d[0]), "+f"(d[1]), "+f"(d[2]), "+f"(d[3])
        : "r"(a[0]), "r"(a[1]), "r"(a[2]), "r"(a[3]), "r"(b0), "r"(b1));
}

__device__ __forceinline__ void mma16(float* d, const unsigned* a, unsigned b0, unsigned b1) {
    asm volatile(
        "mma.sync.aligned.m16n8k16.row.col.f32.f16.f16.f32 "
        "{%0,%1,%2,%3},{%4,%5,%6,%7},{%8,%9},{%0,%1,%2,%3};\n"
        : "+f"(d[0]), "+f"(d[1]), "+f"(d[2]), "+f"(d[3])
        : "r"(a[0]), "r"(a[1]), "r"(a[2]), "r"(a[3]), "r"(b0), "r"(b1));
}

__device__ __forceinline__ void cp16s(unsigned saddr, const void* g) {
    asm volatile("cp.async.cg.shared.global [%0], [%1], 16;" :: "r"(saddr), "l"(g));
}
#define CP_COMMIT() asm volatile("cp.async.commit_group;" ::: "memory")
#define CP_WAIT0()  asm volatile("cp.async.wait_group 0;" ::: "memory")

__device__ __forceinline__ unsigned smem_u32(const void* p) {
    unsigned a;
    asm("{ .reg .u64 t; cvta.to.shared.u64 t, %1; cvt.u32.u64 %0, t; }" : "=r"(a) : "l"(p));
    return a;
}

// ============================================================================
// Pack int32 mask -> bitmask.
// ============================================================================
__global__ __launch_bounds__(256) void pack_mask(const int* __restrict__ m,
                                                 unsigned* __restrict__ bits, int n_words)
{
    int w = blockIdx.x * 8 + (threadIdx.x >> 5);
    int lane = threadIdx.x & 31;
    if (w < n_words) {
        int v = m[(size_t)w * 32 + lane];
        unsigned b = __ballot_sync(0xffffffffu, v != 0);
        if (lane == 0) bits[w] = b;
    }
}

// ============================================================================
// tf32 GEMM (the PROVEN 182us version): C = A @ Bw^T + bias
// ============================================================================
__global__ __launch_bounds__(256, 2) void gemm_tf32(
    const float* __restrict__ A, const float* __restrict__ Bw,
    const float* __restrict__ bias, float* __restrict__ C,
    int M, int N, int K)
{
    extern __shared__ float dsm[];

    const int tid  = threadIdx.x;
    const int lane = tid & 31, warp = tid >> 5;
    const int group = lane >> 2, t4 = lane & 3;
    const int wm = warp >> 1, wn = warp & 1;
    const int m0 = blockIdx.y * 128, n0 = blockIdx.x * 128;
    const int lr = tid >> 1, lc = (tid & 1) * 16;

    float acc[2][8][4];
#pragma unroll
    for (int i = 0; i < 2; i++)
#pragma unroll
        for (int j = 0; j < 8; j++)
#pragma unroll
            for (int k = 0; k < 4; k++) acc[i][j][k] = 0.f;

    const float* Ap = A + (size_t)(m0 + lr) * K + lc;
    const float* Bp = Bw + (size_t)(n0 + lr) * K + lc;

    float4 pa[4], pb[4];
#pragma unroll
    for (int j = 0; j < 4; j++) {
        pa[j] = *(const float4*)(Ap + 4 * j);
        pb[j] = *(const float4*)(Bp + 4 * j);
    }
    {
        float* sA0 = dsm;
        float* sB0 = dsm + 9216;
#pragma unroll
        for (int j = 0; j < 4; j++) {
            *(float4*)&sA0[lr * 36 + lc + 4 * j] =
                make_float4(to_tf32(pa[j].x), to_tf32(pa[j].y), to_tf32(pa[j].z), to_tf32(pa[j].w));
            *(float4*)&sB0[lr * 36 + lc + 4 * j] =
                make_float4(to_tf32(pb[j].x), to_tf32(pb[j].y), to_tf32(pb[j].z), to_tf32(pb[j].w));
        }
    }
    __syncthreads();

    const int NC = K / 32;
    for (int c = 0; c < NC; c++) {
        if (c + 1 < NC) {
#pragma unroll
            for (int j = 0; j < 4; j++) {
                pa[j] = *(const float4*)(Ap + (c + 1) * 32 + 4 * j);
                pb[j] = *(const float4*)(Bp + (c + 1) * 32 + 4 * j);
            }
        }
        const float* sAc = dsm + (c & 1) * 4608;
        const float* sBc = dsm + 9216 + (c & 1) * 4608;
#pragma unroll
        for (int kk = 0; kk < 32; kk += 8) {
            unsigned a[2][4];
#pragma unroll
            for (int mf = 0; mf < 2; mf++) {
                int r = wm * 32 + mf * 16 + group;
                a[mf][0] = __float_as_uint(sAc[r * 36 + kk + t4]);
                a[mf][1] = __float_as_uint(sAc[(r + 8) * 36 + kk + t4]);
                a[mf][2] = __float_as_uint(sAc[r * 36 + kk + t4 + 4]);
                a[mf][3] = __float_as_uint(sAc[(r + 8) * 36 + kk + t4 + 4]);
            }
#pragma unroll
            for (int nf = 0; nf < 8; nf++) {
                int n = wn * 64 + nf * 8 + group;
                unsigned b0 = __float_as_uint(sBc[n * 36 + kk + t4]);
                unsigned b1 = __float_as_uint(sBc[n * 36 + kk + t4 + 4]);
#pragma unroll
                for (int mf = 0; mf < 2; mf++) mma8(acc[mf][nf], a[mf], b0, b1);
            }
        }
        if (c + 1 < NC) {
            float* sAn = dsm + ((c + 1) & 1) * 4608;
            float* sBn = dsm + 9216 + ((c + 1) & 1) * 4608;
#pragma unroll
            for (int j = 0; j < 4; j++) {
                *(float4*)&sAn[lr * 36 + lc + 4 * j] =
                    make_float4(to_tf32(pa[j].x), to_tf32(pa[j].y), to_tf32(pa[j].z), to_tf32(pa[j].w));
                *(float4*)&sBn[lr * 36 + lc + 4 * j] =
                    make_float4(to_tf32(pb[j].x), to_tf32(pb[j].y), to_tf32(pb[j].z), to_tf32(pb[j].w));
            }
        }
        __syncthreads();
    }

#pragma unroll
    for (int mf = 0; mf < 2; mf++) {
        int r = m0 + wm * 32 + mf * 16 + group;
#pragma unroll
        for (int nf = 0; nf < 8; nf++) {
            int cc = n0 + wn * 64 + nf * 8 + t4 * 2;
            float b0v = bias[cc], b1v = bias[cc + 1];
            C[(size_t)r * N + cc]           = acc[mf][nf][0] + b0v;
            C[(size_t)r * N + cc + 1]       = acc[mf][nf][1] + b1v;
            C[(size_t)(r + 8) * N + cc]     = acc[mf][nf][2] + b0v;
            C[(size_t)(r + 8) * N + cc + 1] = acc[mf][nf][3] + b1v;
        }
    }
}

// ============================================================================
// Transpose v: g_vproj fp32 [b][s][h*64+d] -> g_vprojTh half [bh][d][s]
// Block = 64s x 64d tile of one (b,h). grid (SEQ/64, B*H).
// ============================================================================
__global__ __launch_bounds__(256) void transpose_v()
{
    __shared__ float t[64][65];
    const int bh = blockIdx.y, b = bh >> 4, h = bh & 15;
    const int s0 = blockIdx.x * 64;
    const int r = threadIdx.x >> 2, c0 = (threadIdx.x & 3) * 16;

    const float* src = g_vproj + ((size_t)b * SEQ + s0 + r) * D_MODEL + h * DK + c0;
#pragma unroll
    for (int j = 0; j < 4; j++) {
        float4 v = *(const float4*)(src + 4 * j);
        t[r][c0 + 4 * j + 0] = v.x; t[r][c0 + 4 * j + 1] = v.y;
        t[r][c0 + 4 * j + 2] = v.z; t[r][c0 + 4 * j + 3] = v.w;
    }
    __syncthreads();

    // now r = d index, c0 = s offset within tile
    __half* dst = g_vprojTh + ((size_t)bh * DK + r) * SEQ + s0 + c0;
    unsigned q[8];
#pragma unroll
    for (int j = 0; j < 8; j++)
        q[j] = pack2h(t[c0 + 2 * j][r], t[c0 + 2 * j + 1][r]);
    *(uint4*)(dst)     = make_uint4(q[0], q[1], q[2], q[3]);
    *(uint4*)(dst + 8) = make_uint4(q[4], q[5], q[6], q[7]);
}

// ============================================================================
// Fused softmax + attention mix, fp16 mma, FULL-LINE-COALESCED W producer.
// R12 finding: mix is L1-wavefront bound; the 2-thr/row W LDG pattern made
// 16 wavefronts per LDG.128 at 25% line utilization. New producer mapping:
// thread t loads float4 at row (t>>3)+32j (j=0..3), col (t&7)*4 — each warp
// instruction covers 4 rows x full 128B line = 4 perfect wavefronts.
// W LDG wf/chunk: 512 -> 128. Everything else (fragment layout, stages,
// barriers, pitch 40, epilogue) identical to the verified R12 kernel.
// Rowsum: 8 lanes per row -> 3 shfl_xor; mask bits per own quarter-line.
// smem halves: P stages @0,@5120 (128x40); V stages @10240,@12800 (64x40);
// rowinv (float[128]) @15360h = byte 30720. Total 31232 B.
// ============================================================================
#define MIX_SMEM_REQ 31232

__global__ __launch_bounds__(256, 2) void mix_fp16(const float* __restrict__ W)
{
    extern __shared__ __half hsm[];
    float* rinv = (float*)(hsm + 15360);

    const int tid  = threadIdx.x;
    const int lane = tid & 31, warp = tid >> 5;
    const int g    = lane >> 2, t4 = lane & 3;
    const int wm = warp >> 1, wn = warp & 1;
    const int bh = blockIdx.y, b = bh >> 4, h = bh & 15;
    const int q0 = blockIdx.x * 128;

    // W producer: thread t -> rows (t>>3)+32j, quarter-line (t&7)*4 floats
    const int prow = tid >> 3, pcol = (tid & 7) * 4;
    const float*    gWr[4];
    const unsigned* Mpr[4];
#pragma unroll
    for (int j = 0; j < 4; j++) {
        int row = prow + 32 * j;
        gWr[j] = W + ((size_t)bh * SEQ + q0 + row) * SEQ + pcol;
        Mpr[j] = g_maskbits + ((size_t)b * SEQ + q0 + row) * (SEQ / 32);
    }
    const unsigned psts = smem_u32(hsm) + (unsigned)(prow * 40 + pcol) * 2;  // stage 0 base

    // V producer: thread t -> row t>>2 (d), granule t&3 (8 halves)
    const int vr = tid >> 2, vg = tid & 3;
    const __half* gV = g_vprojTh + (size_t)bh * DK * SEQ + (size_t)vr * SEQ + vg * 8;
    const unsigned sV0a = smem_u32(hsm + 10240) + (unsigned)(vr * 40 + vg * 8) * 2;

    float acc[2][4][4];
#pragma unroll
    for (int i = 0; i < 2; i++)
#pragma unroll
        for (int j = 0; j < 4; j++)
#pragma unroll
            for (int k = 0; k < 4; k++) acc[i][j][k] = 0.f;

    float ls[4] = {0.f, 0.f, 0.f, 0.f};
    float4 w[4];
    unsigned mw[4];

    // ---- prologue: chunk 0 ----
#pragma unroll
    for (int j = 0; j < 4; j++) { w[j] = __ldcs((const float4*)(gWr[j])); mw[j] = Mpr[j][0]; }
    cp16s(sV0a, gV);                      // V chunk 0 -> stage 0
    CP_COMMIT();
    {   // produce P0 -> stage 0
#pragma unroll
        for (int j = 0; j < 4; j++) {
            float e0 = ((mw[j] >> (pcol + 0)) & 1u) ? __expf(w[j].x) : 0.f;
            float e1 = ((mw[j] >> (pcol + 1)) & 1u) ? __expf(w[j].y) : 0.f;
            float e2 = ((mw[j] >> (pcol + 2)) & 1u) ? __expf(w[j].z) : 0.f;
            float e3 = ((mw[j] >> (pcol + 3)) & 1u) ? __expf(w[j].w) : 0.f;
            ls[j] += (e0 + e1) + (e2 + e3);
            asm volatile("st.shared.v2.b32 [%0], {%1,%2};"
                :: "r"(psts + (unsigned)(j * 32 * 40) * 2),
                   "r"(pack2h(e0, e1)), "r"(pack2h(e2, e3)) : "memory");
        }
    }
#pragma unroll
    for (int j = 0; j < 4; j++) { w[j] = __ldcs((const float4*)(gWr[j] + 32)); mw[j] = Mpr[j][1]; }
    CP_WAIT0();
    __syncthreads();

    // ---- main loop ----
    for (int c = 0; c < 64; c++) {
        // V chunk c+1 -> stage (c+1)&1
        if (c + 1 < 64) {
            cp16s(sV0a + ((c + 1) & 1) * 5120, gV + (size_t)(c + 1) * 32);
            CP_COMMIT();
        }

        // mma on stage c&1
        {
            const __half* sPb = hsm + (c & 1) * 5120;
            const __half* sVb = hsm + 10240 + (c & 1) * 2560;
#pragma unroll
            for (int ks = 0; ks < 32; ks += 16) {
                unsigned a[2][4];
#pragma unroll
                for (int mf = 0; mf < 2; mf++) {
                    int r = wm * 32 + mf * 16 + g;
                    a[mf][0] = *(const unsigned*)(sPb + r * 40 + ks + 2 * t4);
                    a[mf][1] = *(const unsigned*)(sPb + (r + 8) * 40 + ks + 2 * t4);
                    a[mf][2] = *(const unsigned*)(sPb + r * 40 + ks + 2 * t4 + 8);
                    a[mf][3] = *(const unsigned*)(sPb + (r + 8) * 40 + ks + 2 * t4 + 8);
                }
#pragma unroll
                for (int nf = 0; nf < 4; nf++) {
                    int n = wn * 32 + nf * 8 + g;
                    unsigned b0 = *(const unsigned*)(sVb + n * 40 + ks + 2 * t4);
                    unsigned b1 = *(const unsigned*)(sVb + n * 40 + ks + 2 * t4 + 8);
#pragma unroll
                    for (int mf = 0; mf < 2; mf++) mma16(acc[mf][nf], a[mf], b0, b1);
                }
            }
        }

        // produce P(c+1) -> stage (c+1)&1 from regs w (= chunk c+1)
        if (c + 1 < 64) {
            const unsigned pb = psts + ((c + 1) & 1) * 10240;  // 5120 halves * 2B
#pragma unroll
            for (int j = 0; j < 4; j++) {
                float e0 = ((mw[j] >> (pcol + 0)) & 1u) ? __expf(w[j].x) : 0.f;
                float e1 = ((mw[j] >> (pcol + 1)) & 1u) ? __expf(w[j].y) : 0.f;
                float e2 = ((mw[j] >> (pcol + 2)) & 1u) ? __expf(w[j].z) : 0.f;
                float e3 = ((mw[j] >> (pcol + 3)) & 1u) ? __expf(w[j].w) : 0.f;
                ls[j] += (e0 + e1) + (e2 + e3);
                asm volatile("st.shared.v2.b32 [%0], {%1,%2};"
                    :: "r"(pb + (unsigned)(j * 32 * 40) * 2),
                       "r"(pack2h(e0, e1)), "r"(pack2h(e2, e3)) : "memory");
            }
            // LDG W chunk c+2
            if (c + 2 < 64) {
#pragma unroll
                for (int j = 0; j < 4; j++) {
                    w[j] = __ldcs((const float4*)(gWr[j] + (size_t)(c + 2) * 32));
                    mw[j] = Mpr[j][c + 2];
                }
            }
            CP_WAIT0();
        }
        __syncthreads();
    }

    // row sums: 8 lanes per row -> shfl reduce, lane (t&7)==0 writes
#pragma unroll
    for (int j = 0; j < 4; j++) {
        float s = ls[j];
        s += __shfl_xor_sync(0xffffffffu, s, 1);
        s += __shfl_xor_sync(0xffffffffu, s, 2);
        s += __shfl_xor_sync(0xffffffffu, s, 4);
        if ((tid & 7) == 0) rinv[prow + 32 * j] = 1.0f / s;
    }
    __syncthreads();

    // epilogue: scale by 1/rowsum, write x[b, q, h*64 + d] (fp32)
    {
        float* Xb = g_x + (size_t)b * SEQ * D_MODEL + h * DK;
#pragma unroll
        for (int mf = 0; mf < 2; mf++) {
            int rr = wm * 32 + mf * 16 + g;
            float s0 = rinv[rr];
            float s1 = rinv[rr + 8];
            int qr = q0 + rr;
#pragma unroll
            for (int nf = 0; nf < 4; nf++) {
                int n = wn * 32 + nf * 8 + t4 * 2;
                Xb[(size_t)qr * D_MODEL + n]           = acc[mf][nf][0] * s0;
                Xb[(size_t)qr * D_MODEL + n + 1]       = acc[mf][nf][1] * s0;
                Xb[(size_t)(qr + 8) * D_MODEL + n]     = acc[mf][nf][2] * s1;
                Xb[(size_t)(qr + 8) * D_MODEL + n + 1] = acc[mf][nf][3] * s1;
            }
        }
    }
}

// ============================================================================
// Launch: pack mask -> V-proj GEMM (tf32, fp32 out) -> transpose(->half) ->
//         mix -> O-proj GEMM (tf32)
// Inputs: 0 query(unused) 1 key(unused) 2 value 3 weight 4 mask(int32)
//         5 V_w 6 V_b 7 O_w 8 O_b
// ============================================================================
extern "C" void kernel_launch(void* const* d_in, const int* in_sizes, int n_in,
                              void* d_out, int out_size)
{
    const float* value  = (const float*)d_in[2];
    const float* weight = (const float*)d_in[3];
    const int*   mask   = (const int*)d_in[4];
    const float* V_w    = (const float*)d_in[5];
    const float* V_b    = (const float*)d_in[6];
    const float* O_w    = (const float*)d_in[7];
    const float* O_b    = (const float*)d_in[8];
    float* out          = (float*)d_out;

    float *vp, *xp;
    unsigned* mb;
    cudaGetSymbolAddress((void**)&vp, g_vproj);
    cudaGetSymbolAddress((void**)&xp, g_x);
    cudaGetSymbolAddress((void**)&mb, g_maskbits);

    cudaFuncSetAttribute(gemm_tf32, cudaFuncAttributeMaxDynamicSharedMemorySize, 73728);
    cudaFuncSetAttribute(mix_fp16, cudaFuncAttributeMaxDynamicSharedMemorySize, MIX_SMEM_REQ);

    const int n_words = BATCH * SEQ * (SEQ / 32);

    dim3 blk(256);
    dim3 g0((n_words + 7) / 8);
    dim3 g1(D_MODEL / 128, (BATCH * SEQ) / 128);   // (8, 64)
    dim3 gt(SEQ / 64, BATCH * NH);                 // (32, 64)
    dim3 g2(SEQ / 128, BATCH * NH);                // (16, 64)

    pack_mask<<<g0, blk>>>(mask, mb, n_words);
    gemm_tf32<<<g1, blk, 73728>>>(value, V_w, V_b, vp, BATCH * SEQ, D_MODEL, D_MODEL);
    transpose_v<<<gt, blk>>>();
    mix_fp16<<<g2, blk, MIX_SMEM_REQ>>>(weight);
    gemm_tf32<<<g1, blk, 73728>>>(xp, O_w, O_b, out, BATCH * SEQ, D_MODEL, D_MODEL);
}

// round 14
// speedup vs baseline: 1.6496x; 1.1452x over previous
#include <cuda_runtime.h>
#include <cuda_fp16.h>

#define BATCH   4
#define SEQ     2048
#define NH      16
#define DK      64
#define D_MODEL 1024

// Scratch (allocation-free rule: __device__ globals)
__device__ __align__(128) float  g_vproj[(size_t)BATCH * SEQ * D_MODEL];      // fp32 [b][s][h*64+d]
__device__ __align__(128) __half g_vprojTh[(size_t)BATCH * NH * DK * SEQ];    // half [bh][d][s]
__device__ __align__(128) float  g_x[(size_t)BATCH * SEQ * D_MODEL];
__device__ __align__(128) unsigned g_maskbits[(size_t)BATCH * SEQ * (SEQ / 32)];

__device__ __forceinline__ float to_tf32(float x) {
    unsigned u;
    asm("cvt.rna.tf32.f32 %0, %1;" : "=r"(u) : "f"(x));
    return __uint_as_float(u);
}

__device__ __forceinline__ unsigned pack2h(float x, float y) {
    __half2 h = __floats2half2_rn(x, y);
    return *(unsigned*)&h;
}

__device__ __forceinline__ void mma8(float* d, const unsigned* a, unsigned b0, unsigned b1) {
    asm volatile(
        "mma.sync.aligned.m16n8k8.row.col.f32.tf32.tf32.f32 "
        "{%0,%1,%2,%3},{%4,%5,%6,%7},{%8,%9},{%0,%1,%2,%3};\n"
        : "+f"(d[0]), "+f"(d[1]), "+f"(d[2]), "+f"(d[3])
        : "r"(a[0]), "r"(a[1]), "r"(a[2]), "r"(a[3]), "r"(b0), "r"(b1));
}

__device__ __forceinline__ void mma16(float* d, const unsigned* a, unsigned b0, unsigned b1) {
    asm volatile(
        "mma.sync.aligned.m16n8k16.row.col.f32.f16.f16.f32 "
        "{%0,%1,%2,%3},{%4,%5,%6,%7},{%8,%9},{%0,%1,%2,%3};\n"
        : "+f"(d[0]), "+f"(d[1]), "+f"(d[2]), "+f"(d[3])
        : "r"(a[0]), "r"(a[1]), "r"(a[2]), "r"(a[3]), "r"(b0), "r"(b1));
}

__device__ __forceinline__ void cp16s(unsigned saddr, const void* g) {
    asm volatile("cp.async.cg.shared.global [%0], [%1], 16;" :: "r"(saddr), "l"(g));
}
#define CP_COMMIT() asm volatile("cp.async.commit_group;" ::: "memory")
#define CP_WAIT0()  asm volatile("cp.async.wait_group 0;" ::: "memory")

__device__ __forceinline__ unsigned smem_u32(const void* p) {
    unsigned a;
    asm("{ .reg .u64 t; cvta.to.shared.u64 t, %1; cvt.u32.u64 %0, t; }" : "=r"(a) : "l"(p));
    return a;
}

// ============================================================================
// Pack int32 mask -> bitmask.
// ============================================================================
__global__ __launch_bounds__(256) void pack_mask(const int* __restrict__ m,
                                                 unsigned* __restrict__ bits, int n_words)
{
    int w = blockIdx.x * 8 + (threadIdx.x >> 5);
    int lane = threadIdx.x & 31;
    if (w < n_words) {
        int v = m[(size_t)w * 32 + lane];
        unsigned b = __ballot_sync(0xffffffffu, v != 0);
        if (lane == 0) bits[w] = b;
    }
}

// ============================================================================
// tf32 GEMM with FULL-LINE-COALESCED loads (R13's mix fix ported here).
// C[M,N] = A[M,K] @ Bw[N,K]^T + bias[N].
// Loader: thread t -> float4 at row (t>>3)+32j (j=0..3), col (t&7)*4:
//   8 lanes x 16 B = one full 128 B line, 4 wavefronts per warp instruction
//   (was: 2 thr/row 16-float slivers = 16 wf at 25% utilization).
// Fragment/mma side and smem layout (pitch 36, double-buffered) unchanged
// from the proven 182us kernel.
// ============================================================================
__global__ __launch_bounds__(256, 2) void gemm_tf32(
    const float* __restrict__ A, const float* __restrict__ Bw,
    const float* __restrict__ bias, float* __restrict__ C,
    int M, int N, int K)
{
    extern __shared__ float dsm[];

    const int tid  = threadIdx.x;
    const int lane = tid & 31, warp = tid >> 5;
    const int group = lane >> 2, t4 = lane & 3;
    const int wm = warp >> 1, wn = warp & 1;
    const int m0 = blockIdx.y * 128, n0 = blockIdx.x * 128;

    // coalesced loader mapping
    const int pr = tid >> 3, pc = (tid & 7) * 4;

    float acc[2][8][4];
#pragma unroll
    for (int i = 0; i < 2; i++)
#pragma unroll
        for (int j = 0; j < 8; j++)
#pragma unroll
            for (int k = 0; k < 4; k++) acc[i][j][k] = 0.f;

    const float* Ap = A + (size_t)(m0 + pr) * K + pc;
    const float* Bp = Bw + (size_t)(n0 + pr) * K + pc;

    float4 pa[4], pb[4];
#pragma unroll
    for (int j = 0; j < 4; j++) {
        pa[j] = *(const float4*)(Ap + (size_t)(32 * j) * K);
        pb[j] = *(const float4*)(Bp + (size_t)(32 * j) * K);
    }
    {
        float* sA0 = dsm;
        float* sB0 = dsm + 9216;
#pragma unroll
        for (int j = 0; j < 4; j++) {
            *(float4*)&sA0[(pr + 32 * j) * 36 + pc] =
                make_float4(to_tf32(pa[j].x), to_tf32(pa[j].y), to_tf32(pa[j].z), to_tf32(pa[j].w));
            *(float4*)&sB0[(pr + 32 * j) * 36 + pc] =
                make_float4(to_tf32(pb[j].x), to_tf32(pb[j].y), to_tf32(pb[j].z), to_tf32(pb[j].w));
        }
    }
    __syncthreads();

    const int NC = K / 32;
    for (int c = 0; c < NC; c++) {
        if (c + 1 < NC) {
#pragma unroll
            for (int j = 0; j < 4; j++) {
                pa[j] = *(const float4*)(Ap + (size_t)(32 * j) * K + (c + 1) * 32);
                pb[j] = *(const float4*)(Bp + (size_t)(32 * j) * K + (c + 1) * 32);
            }
        }
        const float* sAc = dsm + (c & 1) * 4608;
        const float* sBc = dsm + 9216 + (c & 1) * 4608;
#pragma unroll
        for (int kk = 0; kk < 32; kk += 8) {
            unsigned a[2][4];
#pragma unroll
            for (int mf = 0; mf < 2; mf++) {
                int r = wm * 32 + mf * 16 + group;
                a[mf][0] = __float_as_uint(sAc[r * 36 + kk + t4]);
                a[mf][1] = __float_as_uint(sAc[(r + 8) * 36 + kk + t4]);
                a[mf][2] = __float_as_uint(sAc[r * 36 + kk + t4 + 4]);
                a[mf][3] = __float_as_uint(sAc[(r + 8) * 36 + kk + t4 + 4]);
            }
#pragma unroll
            for (int nf = 0; nf < 8; nf++) {
                int n = wn * 64 + nf * 8 + group;
                unsigned b0 = __float_as_uint(sBc[n * 36 + kk + t4]);
                unsigned b1 = __float_as_uint(sBc[n * 36 + kk + t4 + 4]);
#pragma unroll
                for (int mf = 0; mf < 2; mf++) mma8(acc[mf][nf], a[mf], b0, b1);
            }
        }
        if (c + 1 < NC) {
            float* sAn = dsm + ((c + 1) & 1) * 4608;
            float* sBn = dsm + 9216 + ((c + 1) & 1) * 4608;
#pragma unroll
            for (int j = 0; j < 4; j++) {
                *(float4*)&sAn[(pr + 32 * j) * 36 + pc] =
                    make_float4(to_tf32(pa[j].x), to_tf32(pa[j].y), to_tf32(pa[j].z), to_tf32(pa[j].w));
                *(float4*)&sBn[(pr + 32 * j) * 36 + pc] =
                    make_float4(to_tf32(pb[j].x), to_tf32(pb[j].y), to_tf32(pb[j].z), to_tf32(pb[j].w));
            }
        }
        __syncthreads();
    }

#pragma unroll
    for (int mf = 0; mf < 2; mf++) {
        int r = m0 + wm * 32 + mf * 16 + group;
#pragma unroll
        for (int nf = 0; nf < 8; nf++) {
            int cc = n0 + wn * 64 + nf * 8 + t4 * 2;
            float b0v = bias[cc], b1v = bias[cc + 1];
            C[(size_t)r * N + cc]           = acc[mf][nf][0] + b0v;
            C[(size_t)r * N + cc + 1]       = acc[mf][nf][1] + b1v;
            C[(size_t)(r + 8) * N + cc]     = acc[mf][nf][2] + b0v;
            C[(size_t)(r + 8) * N + cc + 1] = acc[mf][nf][3] + b1v;
        }
    }
}

// ============================================================================
// Transpose v: g_vproj fp32 [b][s][h*64+d] -> g_vprojTh half [bh][d][s]
// Block = 64s x 64d tile of one (b,h). grid (SEQ/64, B*H).
// ============================================================================
__global__ __launch_bounds__(256) void transpose_v()
{
    __shared__ float t[64][65];
    const int bh = blockIdx.y, b = bh >> 4, h = bh & 15;
    const int s0 = blockIdx.x * 64;
    const int r = threadIdx.x >> 2, c0 = (threadIdx.x & 3) * 16;

    const float* src = g_vproj + ((size_t)b * SEQ + s0 + r) * D_MODEL + h * DK + c0;
#pragma unroll
    for (int j = 0; j < 4; j++) {
        float4 v = *(const float4*)(src + 4 * j);
        t[r][c0 + 4 * j + 0] = v.x; t[r][c0 + 4 * j + 1] = v.y;
        t[r][c0 + 4 * j + 2] = v.z; t[r][c0 + 4 * j + 3] = v.w;
    }
    __syncthreads();

    // now r = d index, c0 = s offset within tile
    __half* dst = g_vprojTh + ((size_t)bh * DK + r) * SEQ + s0 + c0;
    unsigned q[8];
#pragma unroll
    for (int j = 0; j < 8; j++)
        q[j] = pack2h(t[c0 + 2 * j][r], t[c0 + 2 * j + 1][r]);
    *(uint4*)(dst)     = make_uint4(q[0], q[1], q[2], q[3]);
    *(uint4*)(dst + 8) = make_uint4(q[4], q[5], q[6], q[7]);
}

// ============================================================================
// Fused softmax + attention mix, fp16 mma, full-line-coalesced W producer.
// (UNCHANGED from the verified 271us R13 kernel.)
// smem halves: P stages @0,@5120 (128x40); V stages @10240,@12800 (64x40);
// rowinv (float[128]) @15360h = byte 30720. Total 31232 B.
// ============================================================================
#define MIX_SMEM_REQ 31232

__global__ __launch_bounds__(256, 2) void mix_fp16(const float* __restrict__ W)
{
    extern __shared__ __half hsm[];
    float* rinv = (float*)(hsm + 15360);

    const int tid  = threadIdx.x;
    const int lane = tid & 31, warp = tid >> 5;
    const int g    = lane >> 2, t4 = lane & 3;
    const int wm = warp >> 1, wn = warp & 1;
    const int bh = blockIdx.y, b = bh >> 4, h = bh & 15;
    const int q0 = blockIdx.x * 128;

    // W producer: thread t -> rows (t>>3)+32j, quarter-line (t&7)*4 floats
    const int prow = tid >> 3, pcol = (tid & 7) * 4;
    const float*    gWr[4];
    const unsigned* Mpr[4];
#pragma unroll
    for (int j = 0; j < 4; j++) {
        int row = prow + 32 * j;
        gWr[j] = W + ((size_t)bh * SEQ + q0 + row) * SEQ + pcol;
        Mpr[j] = g_maskbits + ((size_t)b * SEQ + q0 + row) * (SEQ / 32);
    }
    const unsigned psts = smem_u32(hsm) + (unsigned)(prow * 40 + pcol) * 2;  // stage 0 base

    // V producer: thread t -> row t>>2 (d), granule t&3 (8 halves)
    const int vr = tid >> 2, vg = tid & 3;
    const __half* gV = g_vprojTh + (size_t)bh * DK * SEQ + (size_t)vr * SEQ + vg * 8;
    const unsigned sV0a = smem_u32(hsm + 10240) + (unsigned)(vr * 40 + vg * 8) * 2;

    float acc[2][4][4];
#pragma unroll
    for (int i = 0; i < 2; i++)
#pragma unroll
        for (int j = 0; j < 4; j++)
#pragma unroll
            for (int k = 0; k < 4; k++) acc[i][j][k] = 0.f;

    float ls[4] = {0.f, 0.f, 0.f, 0.f};
    float4 w[4];
    unsigned mw[4];

    // ---- prologue: chunk 0 ----
#pragma unroll
    for (int j = 0; j < 4; j++) { w[j] = __ldcs((const float4*)(gWr[j])); mw[j] = Mpr[j][0]; }
    cp16s(sV0a, gV);                      // V chunk 0 -> stage 0
    CP_COMMIT();
    {   // produce P0 -> stage 0
#pragma unroll
        for (int j = 0; j < 4; j++) {
            float e0 = ((mw[j] >> (pcol + 0)) & 1u) ? __expf(w[j].x) : 0.f;
            float e1 = ((mw[j] >> (pcol + 1)) & 1u) ? __expf(w[j].y) : 0.f;
            float e2 = ((mw[j] >> (pcol + 2)) & 1u) ? __expf(w[j].z) : 0.f;
            float e3 = ((mw[j] >> (pcol + 3)) & 1u) ? __expf(w[j].w) : 0.f;
            ls[j] += (e0 + e1) + (e2 + e3);
            asm volatile("st.shared.v2.b32 [%0], {%1,%2};"
                :: "r"(psts + (unsigned)(j * 32 * 40) * 2),
                   "r"(pack2h(e0, e1)), "r"(pack2h(e2, e3)) : "memory");
        }
    }
#pragma unroll
    for (int j = 0; j < 4; j++) { w[j] = __ldcs((const float4*)(gWr[j] + 32)); mw[j] = Mpr[j][1]; }
    CP_WAIT0();
    __syncthreads();

    // ---- main loop ----
    for (int c = 0; c < 64; c++) {
        // V chunk c+1 -> stage (c+1)&1
        if (c + 1 < 64) {
            cp16s(sV0a + ((c + 1) & 1) * 5120, gV + (size_t)(c + 1) * 32);
            CP_COMMIT();
        }

        // mma on stage c&1
        {
            const __half* sPb = hsm + (c & 1) * 5120;
            const __half* sVb = hsm + 10240 + (c & 1) * 2560;
#pragma unroll
            for (int ks = 0; ks < 32; ks += 16) {
                unsigned a[2][4];
#pragma unroll
                for (int mf = 0; mf < 2; mf++) {
                    int r = wm * 32 + mf * 16 + g;
                    a[mf][0] = *(const unsigned*)(sPb + r * 40 + ks + 2 * t4);
                    a[mf][1] = *(const unsigned*)(sPb + (r + 8) * 40 + ks + 2 * t4);
                    a[mf][2] = *(const unsigned*)(sPb + r * 40 + ks + 2 * t4 + 8);
                    a[mf][3] = *(const unsigned*)(sPb + (r + 8) * 40 + ks + 2 * t4 + 8);
                }
#pragma unroll
                for (int nf = 0; nf < 4; nf++) {
                    int n = wn * 32 + nf * 8 + g;
                    unsigned b0 = *(const unsigned*)(sVb + n * 40 + ks + 2 * t4);
                    unsigned b1 = *(const unsigned*)(sVb + n * 40 + ks + 2 * t4 + 8);
#pragma unroll
                    for (int mf = 0; mf < 2; mf++) mma16(acc[mf][nf], a[mf], b0, b1);
                }
            }
        }

        // produce P(c+1) -> stage (c+1)&1 from regs w (= chunk c+1)
        if (c + 1 < 64) {
            const unsigned pb = psts + ((c + 1) & 1) * 10240;  // 5120 halves * 2B
#pragma unroll
            for (int j = 0; j < 4; j++) {
                float e0 = ((mw[j] >> (pcol + 0)) & 1u) ? __expf(w[j].x) : 0.f;
                float e1 = ((mw[j] >> (pcol + 1)) & 1u) ? __expf(w[j].y) : 0.f;
                float e2 = ((mw[j] >> (pcol + 2)) & 1u) ? __expf(w[j].z) : 0.f;
                float e3 = ((mw[j] >> (pcol + 3)) & 1u) ? __expf(w[j].w) : 0.f;
                ls[j] += (e0 + e1) + (e2 + e3);
                asm volatile("st.shared.v2.b32 [%0], {%1,%2};"
                    :: "r"(pb + (unsigned)(j * 32 * 40) * 2),
                       "r"(pack2h(e0, e1)), "r"(pack2h(e2, e3)) : "memory");
            }
            // LDG W chunk c+2
            if (c + 2 < 64) {
#pragma unroll
                for (int j = 0; j < 4; j++) {
                    w[j] = __ldcs((const float4*)(gWr[j] + (size_t)(c + 2) * 32));
                    mw[j] = Mpr[j][c + 2];
                }
            }
            CP_WAIT0();
        }
        __syncthreads();
    }

    // row sums: 8 lanes per row -> shfl reduce, lane (t&7)==0 writes
#pragma unroll
    for (int j = 0; j < 4; j++) {
        float s = ls[j];
        s += __shfl_xor_sync(0xffffffffu, s, 1);
        s += __shfl_xor_sync(0xffffffffu, s, 2);
        s += __shfl_xor_sync(0xffffffffu, s, 4);
        if ((tid & 7) == 0) rinv[prow + 32 * j] = 1.0f / s;
    }
    __syncthreads();

    // epilogue: scale by 1/rowsum, write x[b, q, h*64 + d] (fp32)
    {
        float* Xb = g_x + (size_t)b * SEQ * D_MODEL + h * DK;
#pragma unroll
        for (int mf = 0; mf < 2; mf++) {
            int rr = wm * 32 + mf * 16 + g;
            float s0 = rinv[rr];
            float s1 = rinv[rr + 8];
            int qr = q0 + rr;
#pragma unroll
            for (int nf = 0; nf < 4; nf++) {
                int n = wn * 32 + nf * 8 + t4 * 2;
                Xb[(size_t)qr * D_MODEL + n]           = acc[mf][nf][0] * s0;
                Xb[(size_t)qr * D_MODEL + n + 1]       = acc[mf][nf][1] * s0;
                Xb[(size_t)(qr + 8) * D_MODEL + n]     = acc[mf][nf][2] * s1;
                Xb[(size_t)(qr + 8) * D_MODEL + n + 1] = acc[mf][nf][3] * s1;
            }
        }
    }
}

// ============================================================================
// Launch: pack mask -> V-proj GEMM (tf32, fp32 out) -> transpose(->half) ->
//         mix -> O-proj GEMM (tf32)
// Inputs: 0 query(unused) 1 key(unused) 2 value 3 weight 4 mask(int32)
//         5 V_w 6 V_b 7 O_w 8 O_b
// ============================================================================
extern "C" void kernel_launch(void* const* d_in, const int* in_sizes, int n_in,
                              void* d_out, int out_size)
{
    const float* value  = (const float*)d_in[2];
    const float* weight = (const float*)d_in[3];
    const int*   mask   = (const int*)d_in[4];
    const float* V_w    = (const float*)d_in[5];
    const float* V_b    = (const float*)d_in[6];
    const float* O_w    = (const float*)d_in[7];
    const float* O_b    = (const float*)d_in[8];
    float* out          = (float*)d_out;

    float *vp, *xp;
    unsigned* mb;
    cudaGetSymbolAddress((void**)&vp, g_vproj);
    cudaGetSymbolAddress((void**)&xp, g_x);
    cudaGetSymbolAddress((void**)&mb, g_maskbits);

    cudaFuncSetAttribute(gemm_tf32, cudaFuncAttributeMaxDynamicSharedMemorySize, 73728);
    cudaFuncSetAttribute(mix_fp16, cudaFuncAttributeMaxDynamicSharedMemorySize, MIX_SMEM_REQ);

    const int n_words = BATCH * SEQ * (SEQ / 32);

    dim3 blk(256);
    dim3 g0((n_words + 7) / 8);
    dim3 g1(D_MODEL / 128, (BATCH * SEQ) / 128);   // (8, 64)
    dim3 gt(SEQ / 64, BATCH * NH);                 // (32, 64)
    dim3 g2(SEQ / 128, BATCH * NH);                // (16, 64)

    pack_mask<<<g0, blk>>>(mask, mb, n_words);
    gemm_tf32<<<g1, blk, 73728>>>(value, V_w, V_b, vp, BATCH * SEQ, D_MODEL, D_MODEL);
    transpose_v<<<gt, blk>>>();
    mix_fp16<<<g2, blk, MIX_SMEM_REQ>>>(weight);
    gemm_tf32<<<g1, blk, 73728>>>(xp, O_w, O_b, out, BATCH * SEQ, D_MODEL, D_MODEL);
}

// round 15
// speedup vs baseline: 1.9503x; 1.1823x over previous
#include <cuda_runtime.h>
#include <cuda_fp16.h>

#define BATCH   4
#define SEQ     2048
#define NH      16
#define DK      64
#define D_MODEL 1024

// Scratch (allocation-free rule: __device__ globals)
__device__ __align__(128) float  g_vproj[(size_t)BATCH * SEQ * D_MODEL];      // fp32 [b][s][h*64+d]
__device__ __align__(128) __half g_vprojTh[(size_t)BATCH * NH * DK * SEQ];    // half [bh][d][s]
__device__ __align__(128) float  g_x[(size_t)BATCH * SEQ * D_MODEL];
__device__ __align__(128) unsigned g_maskbits[(size_t)BATCH * SEQ * (SEQ / 32)];

__device__ __forceinline__ unsigned pack2h(float x, float y) {
    __half2 h = __floats2half2_rn(x, y);
    return *(unsigned*)&h;
}

__device__ __forceinline__ void mma16(float* d, const unsigned* a, unsigned b0, unsigned b1) {
    asm volatile(
        "mma.sync.aligned.m16n8k16.row.col.f32.f16.f16.f32 "
        "{%0,%1,%2,%3},{%4,%5,%6,%7},{%8,%9},{%0,%1,%2,%3};\n"
        : "+f"(d[0]), "+f"(d[1]), "+f"(d[2]), "+f"(d[3])
        : "r"(a[0]), "r"(a[1]), "r"(a[2]), "r"(a[3]), "r"(b0), "r"(b1));
}

__device__ __forceinline__ void cp16s(unsigned saddr, const void* g) {
    asm volatile("cp.async.cg.shared.global [%0], [%1], 16;" :: "r"(saddr), "l"(g));
}
#define CP_COMMIT() asm volatile("cp.async.commit_group;" ::: "memory")
#define CP_WAIT0()  asm volatile("cp.async.wait_group 0;" ::: "memory")

__device__ __forceinline__ unsigned smem_u32(const void* p) {
    unsigned a;
    asm("{ .reg .u64 t; cvta.to.shared.u64 t, %1; cvt.u32.u64 %0, t; }" : "=r"(a) : "l"(p));
    return a;
}

// ============================================================================
// Pack int32 mask -> bitmask.
// ============================================================================
__global__ __launch_bounds__(256) void pack_mask(const int* __restrict__ m,
                                                 unsigned* __restrict__ bits, int n_words)
{
    int w = blockIdx.x * 8 + (threadIdx.x >> 5);
    int lane = threadIdx.x & 31;
    if (w < n_words) {
        int v = m[(size_t)w * 32 + lane];
        unsigned b = __ballot_sync(0xffffffffu, v != 0);
        if (lane == 0) bits[w] = b;
    }
}

// ============================================================================
// fp16 GEMM on the coalesced skeleton: C[M,N] = A[M,K] @ Bw[N,K]^T + bias[N].
// Same control flow as the proven 139us tf32 kernel; fp16 operands via
// m16n8k16 (half the mma instructions + half the fragment LDS bytes),
// fp32 accumulate, fp32 C + bias.
// Loader: thread t -> float4 at row (t>>3)+32j (j=0..3), col (t&7)*4
// (full 128B lines), packed to 2x half2, STS.64 into pitch-40-half stages.
// Fragment addressing identical to the verified mix_fp16 scheme.
// smem halves: sA stages @0,@5120 ; sB stages @10240,@15360. 40960 B.
// ============================================================================
__global__ __launch_bounds__(256, 2) void gemm_fp16(
    const float* __restrict__ A, const float* __restrict__ Bw,
    const float* __restrict__ bias, float* __restrict__ C,
    int M, int N, int K)
{
    extern __shared__ __half hsm[];

    const int tid  = threadIdx.x;
    const int lane = tid & 31, warp = tid >> 5;
    const int g    = lane >> 2, t4 = lane & 3;
    const int wm = warp >> 1, wn = warp & 1;
    const int m0 = blockIdx.y * 128, n0 = blockIdx.x * 128;

    // coalesced loader mapping
    const int pr = tid >> 3, pc = (tid & 7) * 4;

    float acc[2][8][4];
#pragma unroll
    for (int i = 0; i < 2; i++)
#pragma unroll
        for (int j = 0; j < 8; j++)
#pragma unroll
            for (int k = 0; k < 4; k++) acc[i][j][k] = 0.f;

    const float* Ap = A + (size_t)(m0 + pr) * K + pc;
    const float* Bp = Bw + (size_t)(n0 + pr) * K + pc;

    float4 pa[4], pb[4];
#pragma unroll
    for (int j = 0; j < 4; j++) {
        pa[j] = *(const float4*)(Ap + (size_t)(32 * j) * K);
        pb[j] = *(const float4*)(Bp + (size_t)(32 * j) * K);
    }
    {
        __half* sA = hsm;
        __half* sB = hsm + 10240;
#pragma unroll
        for (int j = 0; j < 4; j++) {
            *(uint2*)(sA + (pr + 32 * j) * 40 + pc) =
                make_uint2(pack2h(pa[j].x, pa[j].y), pack2h(pa[j].z, pa[j].w));
            *(uint2*)(sB + (pr + 32 * j) * 40 + pc) =
                make_uint2(pack2h(pb[j].x, pb[j].y), pack2h(pb[j].z, pb[j].w));
        }
    }
    __syncthreads();

    const int NC = K / 32;
    for (int c = 0; c < NC; c++) {
        if (c + 1 < NC) {
#pragma unroll
            for (int j = 0; j < 4; j++) {
                pa[j] = *(const float4*)(Ap + (size_t)(32 * j) * K + (c + 1) * 32);
                pb[j] = *(const float4*)(Bp + (size_t)(32 * j) * K + (c + 1) * 32);
            }
        }
        const __half* sAc = hsm + (c & 1) * 5120;
        const __half* sBc = hsm + 10240 + (c & 1) * 5120;
#pragma unroll
        for (int ks = 0; ks < 32; ks += 16) {
            unsigned a[2][4];
#pragma unroll
            for (int mf = 0; mf < 2; mf++) {
                int r = wm * 32 + mf * 16 + g;
                a[mf][0] = *(const unsigned*)(sAc + r * 40 + ks + 2 * t4);
                a[mf][1] = *(const unsigned*)(sAc + (r + 8) * 40 + ks + 2 * t4);
                a[mf][2] = *(const unsigned*)(sAc + r * 40 + ks + 2 * t4 + 8);
                a[mf][3] = *(const unsigned*)(sAc + (r + 8) * 40 + ks + 2 * t4 + 8);
            }
#pragma unroll
            for (int nf = 0; nf < 8; nf++) {
                int n = wn * 64 + nf * 8 + g;
                unsigned b0 = *(const unsigned*)(sBc + n * 40 + ks + 2 * t4);
                unsigned b1 = *(const unsigned*)(sBc + n * 40 + ks + 2 * t4 + 8);
#pragma unroll
                for (int mf = 0; mf < 2; mf++) mma16(acc[mf][nf], a[mf], b0, b1);
            }
        }
        if (c + 1 < NC) {
            __half* sAn = hsm + ((c + 1) & 1) * 5120;
            __half* sBn = hsm + 10240 + ((c + 1) & 1) * 5120;
#pragma unroll
            for (int j = 0; j < 4; j++) {
                *(uint2*)(sAn + (pr + 32 * j) * 40 + pc) =
                    make_uint2(pack2h(pa[j].x, pa[j].y), pack2h(pa[j].z, pa[j].w));
                *(uint2*)(sBn + (pr + 32 * j) * 40 + pc) =
                    make_uint2(pack2h(pb[j].x, pb[j].y), pack2h(pb[j].z, pb[j].w));
            }
        }
        __syncthreads();
    }

#pragma unroll
    for (int mf = 0; mf < 2; mf++) {
        int r = m0 + wm * 32 + mf * 16 + g;
#pragma unroll
        for (int nf = 0; nf < 8; nf++) {
            int cc = n0 + wn * 64 + nf * 8 + t4 * 2;
            float b0v = bias[cc], b1v = bias[cc + 1];
            C[(size_t)r * N + cc]           = acc[mf][nf][0] + b0v;
            C[(size_t)r * N + cc + 1]       = acc[mf][nf][1] + b1v;
            C[(size_t)(r + 8) * N + cc]     = acc[mf][nf][2] + b0v;
            C[(size_t)(r + 8) * N + cc + 1] = acc[mf][nf][3] + b1v;
        }
    }
}

// ============================================================================
// Transpose v: g_vproj fp32 [b][s][h*64+d] -> g_vprojTh half [bh][d][s]
// Block = 64s x 64d tile of one (b,h). grid (SEQ/64, B*H).
// ============================================================================
__global__ __launch_bounds__(256) void transpose_v()
{
    __shared__ float t[64][65];
    const int bh = blockIdx.y, b = bh >> 4, h = bh & 15;
    const int s0 = blockIdx.x * 64;
    const int r = threadIdx.x >> 2, c0 = (threadIdx.x & 3) * 16;

    const float* src = g_vproj + ((size_t)b * SEQ + s0 + r) * D_MODEL + h * DK + c0;
#pragma unroll
    for (int j = 0; j < 4; j++) {
        float4 v = *(const float4*)(src + 4 * j);
        t[r][c0 + 4 * j + 0] = v.x; t[r][c0 + 4 * j + 1] = v.y;
        t[r][c0 + 4 * j + 2] = v.z; t[r][c0 + 4 * j + 3] = v.w;
    }
    __syncthreads();

    // now r = d index, c0 = s offset within tile
    __half* dst = g_vprojTh + ((size_t)bh * DK + r) * SEQ + s0 + c0;
    unsigned q[8];
#pragma unroll
    for (int j = 0; j < 8; j++)
        q[j] = pack2h(t[c0 + 2 * j][r], t[c0 + 2 * j + 1][r]);
    *(uint4*)(dst)     = make_uint4(q[0], q[1], q[2], q[3]);
    *(uint4*)(dst + 8) = make_uint4(q[4], q[5], q[6], q[7]);
}

// ============================================================================
// Fused softmax + attention mix, fp16 mma, full-line-coalesced W producer.
// (UNCHANGED from the verified 271us kernel.)
// smem halves: P stages @0,@5120 (128x40); V stages @10240,@12800 (64x40);
// rowinv (float[128]) @15360h = byte 30720. Total 31232 B.
// ============================================================================
#define MIX_SMEM_REQ 31232

__global__ __launch_bounds__(256, 2) void mix_fp16(const float* __restrict__ W)
{
    extern __shared__ __half hsm[];
    float* rinv = (float*)(hsm + 15360);

    const int tid  = threadIdx.x;
    const int lane = tid & 31, warp = tid >> 5;
    const int g    = lane >> 2, t4 = lane & 3;
    const int wm = warp >> 1, wn = warp & 1;
    const int bh = blockIdx.y, b = bh >> 4, h = bh & 15;
    const int q0 = blockIdx.x * 128;

    // W producer: thread t -> rows (t>>3)+32j, quarter-line (t&7)*4 floats
    const int prow = tid >> 3, pcol = (tid & 7) * 4;
    const float*    gWr[4];
    const unsigned* Mpr[4];
#pragma unroll
    for (int j = 0; j < 4; j++) {
        int row = prow + 32 * j;
        gWr[j] = W + ((size_t)bh * SEQ + q0 + row) * SEQ + pcol;
        Mpr[j] = g_maskbits + ((size_t)b * SEQ + q0 + row) * (SEQ / 32);
    }
    const unsigned psts = smem_u32(hsm) + (unsigned)(prow * 40 + pcol) * 2;  // stage 0 base

    // V producer: thread t -> row t>>2 (d), granule t&3 (8 halves)
    const int vr = tid >> 2, vg = tid & 3;
    const __half* gV = g_vprojTh + (size_t)bh * DK * SEQ + (size_t)vr * SEQ + vg * 8;
    const unsigned sV0a = smem_u32(hsm + 10240) + (unsigned)(vr * 40 + vg * 8) * 2;

    float acc[2][4][4];
#pragma unroll
    for (int i = 0; i < 2; i++)
#pragma unroll
        for (int j = 0; j < 4; j++)
#pragma unroll
            for (int k = 0; k < 4; k++) acc[i][j][k] = 0.f;

    float ls[4] = {0.f, 0.f, 0.f, 0.f};
    float4 w[4];
    unsigned mw[4];

    // ---- prologue: chunk 0 ----
#pragma unroll
    for (int j = 0; j < 4; j++) { w[j] = __ldcs((const float4*)(gWr[j])); mw[j] = Mpr[j][0]; }
    cp16s(sV0a, gV);                      // V chunk 0 -> stage 0
    CP_COMMIT();
    {   // produce P0 -> stage 0
#pragma unroll
        for (int j = 0; j < 4; j++) {
            float e0 = ((mw[j] >> (pcol + 0)) & 1u) ? __expf(w[j].x) : 0.f;
            float e1 = ((mw[j] >> (pcol + 1)) & 1u) ? __expf(w[j].y) : 0.f;
            float e2 = ((mw[j] >> (pcol + 2)) & 1u) ? __expf(w[j].z) : 0.f;
            float e3 = ((mw[j] >> (pcol + 3)) & 1u) ? __expf(w[j].w) : 0.f;
            ls[j] += (e0 + e1) + (e2 + e3);
            asm volatile("st.shared.v2.b32 [%0], {%1,%2};"
                :: "r"(psts + (unsigned)(j * 32 * 40) * 2),
                   "r"(pack2h(e0, e1)), "r"(pack2h(e2, e3)) : "memory");
        }
    }
#pragma unroll
    for (int j = 0; j < 4; j++) { w[j] = __ldcs((const float4*)(gWr[j] + 32)); mw[j] = Mpr[j][1]; }
    CP_WAIT0();
    __syncthreads();

    // ---- main loop ----
    for (int c = 0; c < 64; c++) {
        // V chunk c+1 -> stage (c+1)&1
        if (c + 1 < 64) {
            cp16s(sV0a + ((c + 1) & 1) * 5120, gV + (size_t)(c + 1) * 32);
            CP_COMMIT();
        }

        // mma on stage c&1
        {
            const __half* sPb = hsm + (c & 1) * 5120;
            const __half* sVb = hsm + 10240 + (c & 1) * 2560;
#pragma unroll
            for (int ks = 0; ks < 32; ks += 16) {
                unsigned a[2][4];
#pragma unroll
                for (int mf = 0; mf < 2; mf++) {
                    int r = wm * 32 + mf * 16 + g;
                    a[mf][0] = *(const unsigned*)(sPb + r * 40 + ks + 2 * t4);
                    a[mf][1] = *(const unsigned*)(sPb + (r + 8) * 40 + ks + 2 * t4);
                    a[mf][2] = *(const unsigned*)(sPb + r * 40 + ks + 2 * t4 + 8);
                    a[mf][3] = *(const unsigned*)(sPb + (r + 8) * 40 + ks + 2 * t4 + 8);
                }
#pragma unroll
                for (int nf = 0; nf < 4; nf++) {
                    int n = wn * 32 + nf * 8 + g;
                    unsigned b0 = *(const unsigned*)(sVb + n * 40 + ks + 2 * t4);
                    unsigned b1 = *(const unsigned*)(sVb + n * 40 + ks + 2 * t4 + 8);
#pragma unroll
                    for (int mf = 0; mf < 2; mf++) mma16(acc[mf][nf], a[mf], b0, b1);
                }
            }
        }

        // produce P(c+1) -> stage (c+1)&1 from regs w (= chunk c+1)
        if (c + 1 < 64) {
            const unsigned pb = psts + ((c + 1) & 1) * 10240;  // 5120 halves * 2B
#pragma unroll
            for (int j = 0; j < 4; j++) {
                float e0 = ((mw[j] >> (pcol + 0)) & 1u) ? __expf(w[j].x) : 0.f;
                float e1 = ((mw[j] >> (pcol + 1)) & 1u) ? __expf(w[j].y) : 0.f;
                float e2 = ((mw[j] >> (pcol + 2)) & 1u) ? __expf(w[j].z) : 0.f;
                float e3 = ((mw[j] >> (pcol + 3)) & 1u) ? __expf(w[j].w) : 0.f;
                ls[j] += (e0 + e1) + (e2 + e3);
                asm volatile("st.shared.v2.b32 [%0], {%1,%2};"
                    :: "r"(pb + (unsigned)(j * 32 * 40) * 2),
                       "r"(pack2h(e0, e1)), "r"(pack2h(e2, e3)) : "memory");
            }
            // LDG W chunk c+2
            if (c + 2 < 64) {
#pragma unroll
                for (int j = 0; j < 4; j++) {
                    w[j] = __ldcs((const float4*)(gWr[j] + (size_t)(c + 2) * 32));
                    mw[j] = Mpr[j][c + 2];
                }
            }
            CP_WAIT0();
        }
        __syncthreads();
    }

    // row sums: 8 lanes per row -> shfl reduce, lane (t&7)==0 writes
#pragma unroll
    for (int j = 0; j < 4; j++) {
        float s = ls[j];
        s += __shfl_xor_sync(0xffffffffu, s, 1);
        s += __shfl_xor_sync(0xffffffffu, s, 2);
        s += __shfl_xor_sync(0xffffffffu, s, 4);
        if ((tid & 7) == 0) rinv[prow + 32 * j] = 1.0f / s;
    }
    __syncthreads();

    // epilogue: scale by 1/rowsum, write x[b, q, h*64 + d] (fp32)
    {
        float* Xb = g_x + (size_t)b * SEQ * D_MODEL + h * DK;
#pragma unroll
        for (int mf = 0; mf < 2; mf++) {
            int rr = wm * 32 + mf * 16 + g;
            float s0 = rinv[rr];
            float s1 = rinv[rr + 8];
            int qr = q0 + rr;
#pragma unroll
            for (int nf = 0; nf < 4; nf++) {
                int n = wn * 32 + nf * 8 + t4 * 2;
                Xb[(size_t)qr * D_MODEL + n]           = acc[mf][nf][0] * s0;
                Xb[(size_t)qr * D_MODEL + n + 1]       = acc[mf][nf][1] * s0;
                Xb[(size_t)(qr + 8) * D_MODEL + n]     = acc[mf][nf][2] * s1;
                Xb[(size_t)(qr + 8) * D_MODEL + n + 1] = acc[mf][nf][3] * s1;
            }
        }
    }
}

// ============================================================================
// Launch: pack mask -> V-proj GEMM (fp16) -> transpose(->half) -> mix ->
//         O-proj GEMM (fp16)
// Inputs: 0 query(unused) 1 key(unused) 2 value 3 weight 4 mask(int32)
//         5 V_w 6 V_b 7 O_w 8 O_b
// ============================================================================
extern "C" void kernel_launch(void* const* d_in, const int* in_sizes, int n_in,
                              void* d_out, int out_size)
{
    const float* value  = (const float*)d_in[2];
    const float* weight = (const float*)d_in[3];
    const int*   mask   = (const int*)d_in[4];
    const float* V_w    = (const float*)d_in[5];
    const float* V_b    = (const float*)d_in[6];
    const float* O_w    = (const float*)d_in[7];
    const float* O_b    = (const float*)d_in[8];
    float* out          = (float*)d_out;

    float *vp, *xp;
    unsigned* mb;
    cudaGetSymbolAddress((void**)&vp, g_vproj);
    cudaGetSymbolAddress((void**)&xp, g_x);
    cudaGetSymbolAddress((void**)&mb, g_maskbits);

    cudaFuncSetAttribute(gemm_fp16, cudaFuncAttributeMaxDynamicSharedMemorySize, 40960);
    cudaFuncSetAttribute(mix_fp16, cudaFuncAttributeMaxDynamicSharedMemorySize, MIX_SMEM_REQ);

    const int n_words = BATCH * SEQ * (SEQ / 32);

    dim3 blk(256);
    dim3 g0((n_words + 7) / 8);
    dim3 g1(D_MODEL / 128, (BATCH * SEQ) / 128);   // (8, 64)
    dim3 gt(SEQ / 64, BATCH * NH);                 // (32, 64)
    dim3 g2(SEQ / 128, BATCH * NH);                // (16, 64)

    pack_mask<<<g0, blk>>>(mask, mb, n_words);
    gemm_fp16<<<g1, blk, 40960>>>(value, V_w, V_b, vp, BATCH * SEQ, D_MODEL, D_MODEL);
    transpose_v<<<gt, blk>>>();
    mix_fp16<<<g2, blk, MIX_SMEM_REQ>>>(weight);
    gemm_fp16<<<g1, blk, 40960>>>(xp, O_w, O_b, out, BATCH * SEQ, D_MODEL, D_MODEL);
}

// round 16
// speedup vs baseline: 1.9571x; 1.0035x over previous
#include <cuda_runtime.h>
#include <cuda_fp16.h>

#define BATCH   4
#define SEQ     2048
#define NH      16
#define DK      64
#define D_MODEL 1024

// Scratch (allocation-free rule: __device__ globals)
__device__ __align__(128) __half g_vprojh[(size_t)BATCH * SEQ * D_MODEL];     // half [b][s][h*64+d]
__device__ __align__(128) __half g_vprojTh[(size_t)BATCH * NH * DK * SEQ];    // half [bh][d][s]
__device__ __align__(128) __half g_xh[(size_t)BATCH * SEQ * D_MODEL];         // half [b][s][h*64+d]
__device__ __align__(128) unsigned g_maskbits[(size_t)BATCH * SEQ * (SEQ / 32)];

__device__ __forceinline__ unsigned pack2h(float x, float y) {
    __half2 h = __floats2half2_rn(x, y);
    return *(unsigned*)&h;
}

__device__ __forceinline__ void mma16(float* d, const unsigned* a, unsigned b0, unsigned b1) {
    asm volatile(
        "mma.sync.aligned.m16n8k16.row.col.f32.f16.f16.f32 "
        "{%0,%1,%2,%3},{%4,%5,%6,%7},{%8,%9},{%0,%1,%2,%3};\n"
        : "+f"(d[0]), "+f"(d[1]), "+f"(d[2]), "+f"(d[3])
        : "r"(a[0]), "r"(a[1]), "r"(a[2]), "r"(a[3]), "r"(b0), "r"(b1));
}

__device__ __forceinline__ void cp16s(unsigned saddr, const void* g) {
    asm volatile("cp.async.cg.shared.global [%0], [%1], 16;" :: "r"(saddr), "l"(g));
}
#define CP_COMMIT() asm volatile("cp.async.commit_group;" ::: "memory")
#define CP_WAIT0()  asm volatile("cp.async.wait_group 0;" ::: "memory")

__device__ __forceinline__ unsigned smem_u32(const void* p) {
    unsigned a;
    asm("{ .reg .u64 t; cvta.to.shared.u64 t, %1; cvt.u32.u64 %0, t; }" : "=r"(a) : "l"(p));
    return a;
}

// ============================================================================
// Pack int32 mask -> bitmask.
// ============================================================================
__global__ __launch_bounds__(256) void pack_mask(const int* __restrict__ m,
                                                 unsigned* __restrict__ bits, int n_words)
{
    int w = blockIdx.x * 8 + (threadIdx.x >> 5);
    int lane = threadIdx.x & 31;
    if (w < n_words) {
        int v = m[(size_t)w * 32 + lane];
        unsigned b = __ballot_sync(0xffffffffu, v != 0);
        if (lane == 0) bits[w] = b;
    }
}

// ============================================================================
// fp16 GEMM (coalesced skeleton, proven ~94us): C = A @ Bw^T + bias.
// a_half: A is __half [M,K] (x from the mix) -> load raw, no convert.
//         else A is float [M,K] -> convert to half at STS.
// c_half: write C as __half2 (the V projection feeding the mix); else fp32.
// smem halves: sA stages @0,@5120 ; sB stages @10240,@15360. 40960 B.
// ============================================================================
__global__ __launch_bounds__(256, 2) void gemm_fp16(
    const void* __restrict__ Ax, int a_half,
    const float* __restrict__ Bw, const float* __restrict__ bias,
    void* __restrict__ Cout, int c_half,
    int M, int N, int K)
{
    extern __shared__ __half hsm[];

    const int tid  = threadIdx.x;
    const int lane = tid & 31, warp = tid >> 5;
    const int g    = lane >> 2, t4 = lane & 3;
    const int wm = warp >> 1, wn = warp & 1;
    const int m0 = blockIdx.y * 128, n0 = blockIdx.x * 128;

    // loader mappings
    const int pr = tid >> 3, pc = (tid & 7) * 4;      // fp32: 8 thr/row, float4
    const int prh = tid >> 2, pch = (tid & 3) * 8;    // half: 4 thr/row, uint4(8 halves)

    float acc[2][8][4];
#pragma unroll
    for (int i = 0; i < 2; i++)
#pragma unroll
        for (int j = 0; j < 8; j++)
#pragma unroll
            for (int k = 0; k < 4; k++) acc[i][j][k] = 0.f;

    const float*  Apf = (const float*)Ax + (size_t)(m0 + pr) * K + pc;
    const __half* Aph = (const __half*)Ax + (size_t)(m0 + prh) * K + pch;
    const float*  Bp  = Bw + (size_t)(n0 + pr) * K + pc;

    float4 pa[4], pb[4];
    uint4  qa[2];
    if (a_half) {
#pragma unroll
        for (int j = 0; j < 2; j++) qa[j] = *(const uint4*)(Aph + (size_t)(64 * j) * K);
    } else {
#pragma unroll
        for (int j = 0; j < 4; j++) pa[j] = *(const float4*)(Apf + (size_t)(32 * j) * K);
    }
#pragma unroll
    for (int j = 0; j < 4; j++) pb[j] = *(const float4*)(Bp + (size_t)(32 * j) * K);

    {
        __half* sA = hsm;
        __half* sB = hsm + 10240;
        if (a_half) {
#pragma unroll
            for (int j = 0; j < 2; j++)
                *(uint4*)(sA + (prh + 64 * j) * 40 + pch) = qa[j];
        } else {
#pragma unroll
            for (int j = 0; j < 4; j++)
                *(uint2*)(sA + (pr + 32 * j) * 40 + pc) =
                    make_uint2(pack2h(pa[j].x, pa[j].y), pack2h(pa[j].z, pa[j].w));
        }
#pragma unroll
        for (int j = 0; j < 4; j++)
            *(uint2*)(sB + (pr + 32 * j) * 40 + pc) =
                make_uint2(pack2h(pb[j].x, pb[j].y), pack2h(pb[j].z, pb[j].w));
    }
    __syncthreads();

    const int NC = K / 32;
    for (int c = 0; c < NC; c++) {
        if (c + 1 < NC) {
            if (a_half) {
#pragma unroll
                for (int j = 0; j < 2; j++)
                    qa[j] = *(const uint4*)(Aph + (size_t)(64 * j) * K + (c + 1) * 32);
            } else {
#pragma unroll
                for (int j = 0; j < 4; j++)
                    pa[j] = *(const float4*)(Apf + (size_t)(32 * j) * K + (c + 1) * 32);
            }
#pragma unroll
            for (int j = 0; j < 4; j++)
                pb[j] = *(const float4*)(Bp + (size_t)(32 * j) * K + (c + 1) * 32);
        }
        const __half* sAc = hsm + (c & 1) * 5120;
        const __half* sBc = hsm + 10240 + (c & 1) * 5120;
#pragma unroll
        for (int ks = 0; ks < 32; ks += 16) {
            unsigned a[2][4];
#pragma unroll
            for (int mf = 0; mf < 2; mf++) {
                int r = wm * 32 + mf * 16 + g;
                a[mf][0] = *(const unsigned*)(sAc + r * 40 + ks + 2 * t4);
                a[mf][1] = *(const unsigned*)(sAc + (r + 8) * 40 + ks + 2 * t4);
                a[mf][2] = *(const unsigned*)(sAc + r * 40 + ks + 2 * t4 + 8);
                a[mf][3] = *(const unsigned*)(sAc + (r + 8) * 40 + ks + 2 * t4 + 8);
            }
#pragma unroll
            for (int nf = 0; nf < 8; nf++) {
                int n = wn * 64 + nf * 8 + g;
                unsigned b0 = *(const unsigned*)(sBc + n * 40 + ks + 2 * t4);
                unsigned b1 = *(const unsigned*)(sBc + n * 40 + ks + 2 * t4 + 8);
#pragma unroll
                for (int mf = 0; mf < 2; mf++) mma16(acc[mf][nf], a[mf], b0, b1);
            }
        }
        if (c + 1 < NC) {
            __half* sAn = hsm + ((c + 1) & 1) * 5120;
            __half* sBn = hsm + 10240 + ((c + 1) & 1) * 5120;
            if (a_half) {
#pragma unroll
                for (int j = 0; j < 2; j++)
                    *(uint4*)(sAn + (prh + 64 * j) * 40 + pch) = qa[j];
            } else {
#pragma unroll
                for (int j = 0; j < 4; j++)
                    *(uint2*)(sAn + (pr + 32 * j) * 40 + pc) =
                        make_uint2(pack2h(pa[j].x, pa[j].y), pack2h(pa[j].z, pa[j].w));
            }
#pragma unroll
            for (int j = 0; j < 4; j++)
                *(uint2*)(sBn + (pr + 32 * j) * 40 + pc) =
                    make_uint2(pack2h(pb[j].x, pb[j].y), pack2h(pb[j].z, pb[j].w));
        }
        __syncthreads();
    }

#pragma unroll
    for (int mf = 0; mf < 2; mf++) {
        int r = m0 + wm * 32 + mf * 16 + g;
#pragma unroll
        for (int nf = 0; nf < 8; nf++) {
            int cc = n0 + wn * 64 + nf * 8 + t4 * 2;
            float v00 = acc[mf][nf][0] + bias[cc];
            float v01 = acc[mf][nf][1] + bias[cc + 1];
            float v10 = acc[mf][nf][2] + bias[cc];
            float v11 = acc[mf][nf][3] + bias[cc + 1];
            if (c_half) {
                __half* Ch = (__half*)Cout;
                *(__half2*)(Ch + (size_t)r * N + cc)       = __floats2half2_rn(v00, v01);
                *(__half2*)(Ch + (size_t)(r + 8) * N + cc) = __floats2half2_rn(v10, v11);
            } else {
                float* C = (float*)Cout;
                C[(size_t)r * N + cc]           = v00;
                C[(size_t)r * N + cc + 1]       = v01;
                C[(size_t)(r + 8) * N + cc]     = v10;
                C[(size_t)(r + 8) * N + cc + 1] = v11;
            }
        }
    }
}

// ============================================================================
// Transpose v (half in, half out): g_vprojh [b][s][h*64+d] -> g_vprojTh
// [bh][d][s]. Block = 64s x 64d tile of one (b,h). grid (SEQ/64, B*H).
// ============================================================================
__global__ __launch_bounds__(256) void transpose_v()
{
    __shared__ __half t[64][72];
    const int bh = blockIdx.y, b = bh >> 4, h = bh & 15;
    const int s0 = blockIdx.x * 64;
    const int r = threadIdx.x >> 2, c0 = (threadIdx.x & 3) * 16;

    const __half* src = g_vprojh + ((size_t)b * SEQ + s0 + r) * D_MODEL + h * DK + c0;
    *(uint4*)&t[r][c0]     = *(const uint4*)(src);
    *(uint4*)&t[r][c0 + 8] = *(const uint4*)(src + 8);
    __syncthreads();

    // now r = d index, c0 = s offset within tile
    __half* dst = g_vprojTh + ((size_t)bh * DK + r) * SEQ + s0 + c0;
    unsigned q[8];
#pragma unroll
    for (int j = 0; j < 8; j++) {
        __half2 p = __halves2half2(t[c0 + 2 * j][r], t[c0 + 2 * j + 1][r]);
        q[j] = *(unsigned*)&p;
    }
    *(uint4*)(dst)     = make_uint4(q[0], q[1], q[2], q[3]);
    *(uint4*)(dst + 8) = make_uint4(q[4], q[5], q[6], q[7]);
}

// ============================================================================
// Fused softmax + attention mix, fp16 mma, coalesced W producer.
// (Core identical to the verified 269us kernel; epilogue now writes x as
// half2 -> g_xh, same rounding point as the old fp32-store + loader-cvt.)
// smem halves: P stages @0,@5120 (128x40); V stages @10240,@12800 (64x40);
// rowinv (float[128]) @15360h = byte 30720. Total 31232 B.
// ============================================================================
#define MIX_SMEM_REQ 31232

__global__ __launch_bounds__(256, 2) void mix_fp16(const float* __restrict__ W)
{
    extern __shared__ __half hsm[];
    float* rinv = (float*)(hsm + 15360);

    const int tid  = threadIdx.x;
    const int lane = tid & 31, warp = tid >> 5;
    const int g    = lane >> 2, t4 = lane & 3;
    const int wm = warp >> 1, wn = warp & 1;
    const int bh = blockIdx.y, b = bh >> 4, h = bh & 15;
    const int q0 = blockIdx.x * 128;

    // W producer: thread t -> rows (t>>3)+32j, quarter-line (t&7)*4 floats
    const int prow = tid >> 3, pcol = (tid & 7) * 4;
    const float*    gWr[4];
    const unsigned* Mpr[4];
#pragma unroll
    for (int j = 0; j < 4; j++) {
        int row = prow + 32 * j;
        gWr[j] = W + ((size_t)bh * SEQ + q0 + row) * SEQ + pcol;
        Mpr[j] = g_maskbits + ((size_t)b * SEQ + q0 + row) * (SEQ / 32);
    }
    const unsigned psts = smem_u32(hsm) + (unsigned)(prow * 40 + pcol) * 2;  // stage 0 base

    // V producer: thread t -> row t>>2 (d), granule t&3 (8 halves)
    const int vr = tid >> 2, vg = tid & 3;
    const __half* gV = g_vprojTh + (size_t)bh * DK * SEQ + (size_t)vr * SEQ + vg * 8;
    const unsigned sV0a = smem_u32(hsm + 10240) + (unsigned)(vr * 40 + vg * 8) * 2;

    float acc[2][4][4];
#pragma unroll
    for (int i = 0; i < 2; i++)
#pragma unroll
        for (int j = 0; j < 4; j++)
#pragma unroll
            for (int k = 0; k < 4; k++) acc[i][j][k] = 0.f;

    float ls[4] = {0.f, 0.f, 0.f, 0.f};
    float4 w[4];
    unsigned mw[4];

    // ---- prologue: chunk 0 ----
#pragma unroll
    for (int j = 0; j < 4; j++) { w[j] = __ldcs((const float4*)(gWr[j])); mw[j] = Mpr[j][0]; }
    cp16s(sV0a, gV);                      // V chunk 0 -> stage 0
    CP_COMMIT();
    {   // produce P0 -> stage 0
#pragma unroll
        for (int j = 0; j < 4; j++) {
            float e0 = ((mw[j] >> (pcol + 0)) & 1u) ? __expf(w[j].x) : 0.f;
            float e1 = ((mw[j] >> (pcol + 1)) & 1u) ? __expf(w[j].y) : 0.f;
            float e2 = ((mw[j] >> (pcol + 2)) & 1u) ? __expf(w[j].z) : 0.f;
            float e3 = ((mw[j] >> (pcol + 3)) & 1u) ? __expf(w[j].w) : 0.f;
            ls[j] += (e0 + e1) + (e2 + e3);
            asm volatile("st.shared.v2.b32 [%0], {%1,%2};"
                :: "r"(psts + (unsigned)(j * 32 * 40) * 2),
                   "r"(pack2h(e0, e1)), "r"(pack2h(e2, e3)) : "memory");
        }
    }
#pragma unroll
    for (int j = 0; j < 4; j++) { w[j] = __ldcs((const float4*)(gWr[j] + 32)); mw[j] = Mpr[j][1]; }
    CP_WAIT0();
    __syncthreads();

    // ---- main loop ----
    for (int c = 0; c < 64; c++) {
        // V chunk c+1 -> stage (c+1)&1
        if (c + 1 < 64) {
            cp16s(sV0a + ((c + 1) & 1) * 5120, gV + (size_t)(c + 1) * 32);
            CP_COMMIT();
        }

        // mma on stage c&1
        {
            const __half* sPb = hsm + (c & 1) * 5120;
            const __half* sVb = hsm + 10240 + (c & 1) * 2560;
#pragma unroll
            for (int ks = 0; ks < 32; ks += 16) {
                unsigned a[2][4];
#pragma unroll
                for (int mf = 0; mf < 2; mf++) {
                    int r = wm * 32 + mf * 16 + g;
                    a[mf][0] = *(const unsigned*)(sPb + r * 40 + ks + 2 * t4);
                    a[mf][1] = *(const unsigned*)(sPb + (r + 8) * 40 + ks + 2 * t4);
                    a[mf][2] = *(const unsigned*)(sPb + r * 40 + ks + 2 * t4 + 8);
                    a[mf][3] = *(const unsigned*)(sPb + (r + 8) * 40 + ks + 2 * t4 + 8);
                }
#pragma unroll
                for (int nf = 0; nf < 4; nf++) {
                    int n = wn * 32 + nf * 8 + g;
                    unsigned b0 = *(const unsigned*)(sVb + n * 40 + ks + 2 * t4);
                    unsigned b1 = *(const unsigned*)(sVb + n * 40 + ks + 2 * t4 + 8);
#pragma unroll
                    for (int mf = 0; mf < 2; mf++) mma16(acc[mf][nf], a[mf], b0, b1);
                }
            }
        }

        // produce P(c+1) -> stage (c+1)&1 from regs w (= chunk c+1)
        if (c + 1 < 64) {
            const unsigned pb = psts + ((c + 1) & 1) * 10240;  // 5120 halves * 2B
#pragma unroll
            for (int j = 0; j < 4; j++) {
                float e0 = ((mw[j] >> (pcol + 0)) & 1u) ? __expf(w[j].x) : 0.f;
                float e1 = ((mw[j] >> (pcol + 1)) & 1u) ? __expf(w[j].y) : 0.f;
                float e2 = ((mw[j] >> (pcol + 2)) & 1u) ? __expf(w[j].z) : 0.f;
                float e3 = ((mw[j] >> (pcol + 3)) & 1u) ? __expf(w[j].w) : 0.f;
                ls[j] += (e0 + e1) + (e2 + e3);
                asm volatile("st.shared.v2.b32 [%0], {%1,%2};"
                    :: "r"(pb + (unsigned)(j * 32 * 40) * 2),
                       "r"(pack2h(e0, e1)), "r"(pack2h(e2, e3)) : "memory");
            }
            // LDG W chunk c+2
            if (c + 2 < 64) {
#pragma unroll
                for (int j = 0; j < 4; j++) {
                    w[j] = __ldcs((const float4*)(gWr[j] + (size_t)(c + 2) * 32));
                    mw[j] = Mpr[j][c + 2];
                }
            }
            CP_WAIT0();
        }
        __syncthreads();
    }

    // row sums: 8 lanes per row -> shfl reduce, lane (t&7)==0 writes
#pragma unroll
    for (int j = 0; j < 4; j++) {
        float s = ls[j];
        s += __shfl_xor_sync(0xffffffffu, s, 1);
        s += __shfl_xor_sync(0xffffffffu, s, 2);
        s += __shfl_xor_sync(0xffffffffu, s, 4);
        if ((tid & 7) == 0) rinv[prow + 32 * j] = 1.0f / s;
    }
    __syncthreads();

    // epilogue: scale by 1/rowsum, write x as half [b, q, h*64 + d]
    {
        __half* Xb = g_xh + (size_t)b * SEQ * D_MODEL + h * DK;
#pragma unroll
        for (int mf = 0; mf < 2; mf++) {
            int rr = wm * 32 + mf * 16 + g;
            float s0 = rinv[rr];
            float s1 = rinv[rr + 8];
            int qr = q0 + rr;
#pragma unroll
            for (int nf = 0; nf < 4; nf++) {
                int n = wn * 32 + nf * 8 + t4 * 2;
                *(__half2*)(Xb + (size_t)qr * D_MODEL + n) =
                    __floats2half2_rn(acc[mf][nf][0] * s0, acc[mf][nf][1] * s0);
                *(__half2*)(Xb + (size_t)(qr + 8) * D_MODEL + n) =
                    __floats2half2_rn(acc[mf][nf][2] * s1, acc[mf][nf][3] * s1);
            }
        }
    }
}

// ============================================================================
// Launch: pack mask -> V-proj GEMM (fp32 A, half C) -> transpose(half) ->
//         mix (half x out) -> O-proj GEMM (half A, fp32 C)
// Inputs: 0 query(unused) 1 key(unused) 2 value 3 weight 4 mask(int32)
//         5 V_w 6 V_b 7 O_w 8 O_b
// ============================================================================
extern "C" void kernel_launch(void* const* d_in, const int* in_sizes, int n_in,
                              void* d_out, int out_size)
{
    const float* value  = (const float*)d_in[2];
    const float* weight = (const float*)d_in[3];
    const int*   mask   = (const int*)d_in[4];
    const float* V_w    = (const float*)d_in[5];
    const float* V_b    = (const float*)d_in[6];
    const float* O_w    = (const float*)d_in[7];
    const float* O_b    = (const float*)d_in[8];
    float* out          = (float*)d_out;

    __half *vph, *xph;
    unsigned* mb;
    cudaGetSymbolAddress((void**)&vph, g_vprojh);
    cudaGetSymbolAddress((void**)&xph, g_xh);
    cudaGetSymbolAddress((void**)&mb, g_maskbits);

    cudaFuncSetAttribute(gemm_fp16, cudaFuncAttributeMaxDynamicSharedMemorySize, 40960);
    cudaFuncSetAttribute(mix_fp16, cudaFuncAttributeMaxDynamicSharedMemorySize, MIX_SMEM_REQ);

    const int n_words = BATCH * SEQ * (SEQ / 32);

    dim3 blk(256);
    dim3 g0((n_words + 7) / 8);
    dim3 g1(D_MODEL / 128, (BATCH * SEQ) / 128);   // (8, 64)
    dim3 gt(SEQ / 64, BATCH * NH);                 // (32, 64)
    dim3 g2(SEQ / 128, BATCH * NH);                // (16, 64)

    pack_mask<<<g0, blk>>>(mask, mb, n_words);
    gemm_fp16<<<g1, blk, 40960>>>(value, 0, V_w, V_b, vph, 1, BATCH * SEQ, D_MODEL, D_MODEL);
    transpose_v<<<gt, blk>>>();
    mix_fp16<<<g2, blk, MIX_SMEM_REQ>>>(weight);
    gemm_fp16<<<g1, blk, 40960>>>(xph, 1, O_w, O_b, out, 0, BATCH * SEQ, D_MODEL, D_MODEL);
}

// round 17
// speedup vs baseline: 2.0243x; 1.0343x over previous
#include <cuda_runtime.h>
#include <cuda_fp16.h>

#define BATCH   4
#define SEQ     2048
#define NH      16
#define DK      64
#define D_MODEL 1024

// Scratch (allocation-free rule: __device__ globals)
__device__ __align__(128) __half g_vprojh[(size_t)BATCH * SEQ * D_MODEL];     // half [b][s][h*64+d]
__device__ __align__(128) __half g_vprojTh[(size_t)BATCH * NH * DK * SEQ];    // half [bh][d][s]
__device__ __align__(128) __half g_xh[(size_t)BATCH * SEQ * D_MODEL];         // half [b][s][h*64+d]
__device__ __align__(128) unsigned g_maskbits[(size_t)BATCH * SEQ * (SEQ / 32)];

__device__ __forceinline__ unsigned pack2h(float x, float y) {
    __half2 h = __floats2half2_rn(x, y);
    return *(unsigned*)&h;
}

__device__ __forceinline__ void mma16(float* d, const unsigned* a, unsigned b0, unsigned b1) {
    asm volatile(
        "mma.sync.aligned.m16n8k16.row.col.f32.f16.f16.f32 "
        "{%0,%1,%2,%3},{%4,%5,%6,%7},{%8,%9},{%0,%1,%2,%3};\n"
        : "+f"(d[0]), "+f"(d[1]), "+f"(d[2]), "+f"(d[3])
        : "r"(a[0]), "r"(a[1]), "r"(a[2]), "r"(a[3]), "r"(b0), "r"(b1));
}

// ldmatrix x4: loads 4 8x8 b16 matrices; lane l supplies pointer to row (l&7)
// of matrix (l>>3); output reg j of lane l = matrix j [row l>>2][col 2(l&3)].
__device__ __forceinline__ void ldsm4(unsigned& r0, unsigned& r1, unsigned& r2, unsigned& r3,
                                      unsigned saddr) {
    asm volatile("ldmatrix.sync.aligned.m8n8.x4.shared.b16 {%0,%1,%2,%3}, [%4];"
                 : "=r"(r0), "=r"(r1), "=r"(r2), "=r"(r3) : "r"(saddr));
}

__device__ __forceinline__ void cp16s(unsigned saddr, const void* g) {
    asm volatile("cp.async.cg.shared.global [%0], [%1], 16;" :: "r"(saddr), "l"(g));
}
#define CP_COMMIT() asm volatile("cp.async.commit_group;" ::: "memory")
#define CP_WAIT0()  asm volatile("cp.async.wait_group 0;" ::: "memory")

__device__ __forceinline__ unsigned smem_u32(const void* p) {
    unsigned a;
    asm("{ .reg .u64 t; cvta.to.shared.u64 t, %1; cvt.u32.u64 %0, t; }" : "=r"(a) : "l"(p));
    return a;
}

// ============================================================================
// Pack int32 mask -> bitmask.
// ============================================================================
__global__ __launch_bounds__(256) void pack_mask(const int* __restrict__ m,
                                                 unsigned* __restrict__ bits, int n_words)
{
    int w = blockIdx.x * 8 + (threadIdx.x >> 5);
    int lane = threadIdx.x & 31;
    if (w < n_words) {
        int v = m[(size_t)w * 32 + lane];
        unsigned b = __ballot_sync(0xffffffffu, v != 0);
        if (lane == 0) bits[w] = b;
    }
}

// ============================================================================
// fp16 GEMM, fragment loads via ldmatrix (48 LDS.32 -> 12 LDSM per warp/chunk).
// C = A @ Bw^T + bias. a_half/c_half as before. Values bit-identical to R16.
// smem halves: sA stages @0,@5120 ; sB stages @10240,@15360. 40960 B.
// ============================================================================
__global__ __launch_bounds__(256, 2) void gemm_fp16(
    const void* __restrict__ Ax, int a_half,
    const float* __restrict__ Bw, const float* __restrict__ bias,
    void* __restrict__ Cout, int c_half,
    int M, int N, int K)
{
    extern __shared__ __half hsm[];

    const int tid  = threadIdx.x;
    const int lane = tid & 31, warp = tid >> 5;
    const int g    = lane >> 2, t4 = lane & 3;
    const int wm = warp >> 1, wn = warp & 1;
    const int m0 = blockIdx.y * 128, n0 = blockIdx.x * 128;

    // loader mappings
    const int pr = tid >> 3, pc = (tid & 7) * 4;      // fp32: 8 thr/row, float4
    const int prh = tid >> 2, pch = (tid & 3) * 8;    // half: 4 thr/row, uint4(8 halves)

    // ldmatrix per-lane address components (bytes)
    const int lm_row = lane & 7;
    const unsigned aoff0 = (unsigned)(((wm * 32 + lm_row + ((lane >> 3) & 1) * 8) * 40
                                       + (lane >> 4) * 8) * 2);               // + mf*1280 + ks*2
    const unsigned boff0 = (unsigned)(((wn * 64 + (lane >> 4) * 8 + lm_row) * 40
                                       + ((lane >> 3) & 1) * 8) * 2);         // + pair*1280 + ks*2
    const unsigned sAb = smem_u32(hsm);
    const unsigned sBb = smem_u32(hsm + 10240);

    float acc[2][8][4];
#pragma unroll
    for (int i = 0; i < 2; i++)
#pragma unroll
        for (int j = 0; j < 8; j++)
#pragma unroll
            for (int k = 0; k < 4; k++) acc[i][j][k] = 0.f;

    const float*  Apf = (const float*)Ax + (size_t)(m0 + pr) * K + pc;
    const __half* Aph = (const __half*)Ax + (size_t)(m0 + prh) * K + pch;
    const float*  Bp  = Bw + (size_t)(n0 + pr) * K + pc;

    float4 pa[4], pb[4];
    uint4  qa[2];
    if (a_half) {
#pragma unroll
        for (int j = 0; j < 2; j++) qa[j] = *(const uint4*)(Aph + (size_t)(64 * j) * K);
    } else {
#pragma unroll
        for (int j = 0; j < 4; j++) pa[j] = *(const float4*)(Apf + (size_t)(32 * j) * K);
    }
#pragma unroll
    for (int j = 0; j < 4; j++) pb[j] = *(const float4*)(Bp + (size_t)(32 * j) * K);

    {
        __half* sA = hsm;
        __half* sB = hsm + 10240;
        if (a_half) {
#pragma unroll
            for (int j = 0; j < 2; j++)
                *(uint4*)(sA + (prh + 64 * j) * 40 + pch) = qa[j];
        } else {
#pragma unroll
            for (int j = 0; j < 4; j++)
                *(uint2*)(sA + (pr + 32 * j) * 40 + pc) =
                    make_uint2(pack2h(pa[j].x, pa[j].y), pack2h(pa[j].z, pa[j].w));
        }
#pragma unroll
        for (int j = 0; j < 4; j++)
            *(uint2*)(sB + (pr + 32 * j) * 40 + pc) =
                make_uint2(pack2h(pb[j].x, pb[j].y), pack2h(pb[j].z, pb[j].w));
    }
    __syncthreads();

    const int NC = K / 32;
    for (int c = 0; c < NC; c++) {
        if (c + 1 < NC) {
            if (a_half) {
#pragma unroll
                for (int j = 0; j < 2; j++)
                    qa[j] = *(const uint4*)(Aph + (size_t)(64 * j) * K + (c + 1) * 32);
            } else {
#pragma unroll
                for (int j = 0; j < 4; j++)
                    pa[j] = *(const float4*)(Apf + (size_t)(32 * j) * K + (c + 1) * 32);
            }
#pragma unroll
            for (int j = 0; j < 4; j++)
                pb[j] = *(const float4*)(Bp + (size_t)(32 * j) * K + (c + 1) * 32);
        }
        const unsigned sAc = sAb + (c & 1) * 10240;   // bytes
        const unsigned sBc = sBb + (c & 1) * 10240;
#pragma unroll
        for (int ks = 0; ks < 32; ks += 16) {
            unsigned a[2][4];
#pragma unroll
            for (int mf = 0; mf < 2; mf++)
                ldsm4(a[mf][0], a[mf][1], a[mf][2], a[mf][3],
                      sAc + aoff0 + mf * 1280u + ks * 2u);
            unsigned b[8][2];
#pragma unroll
            for (int p = 0; p < 4; p++)
                ldsm4(b[2 * p][0], b[2 * p][1], b[2 * p + 1][0], b[2 * p + 1][1],
                      sBc + boff0 + p * 1280u + ks * 2u);
#pragma unroll
            for (int nf = 0; nf < 8; nf++)
#pragma unroll
                for (int mf = 0; mf < 2; mf++)
                    mma16(acc[mf][nf], a[mf], b[nf][0], b[nf][1]);
        }
        if (c + 1 < NC) {
            __half* sAn = hsm + ((c + 1) & 1) * 5120;
            __half* sBn = hsm + 10240 + ((c + 1) & 1) * 5120;
            if (a_half) {
#pragma unroll
                for (int j = 0; j < 2; j++)
                    *(uint4*)(sAn + (prh + 64 * j) * 40 + pch) = qa[j];
            } else {
#pragma unroll
                for (int j = 0; j < 4; j++)
                    *(uint2*)(sAn + (pr + 32 * j) * 40 + pc) =
                        make_uint2(pack2h(pa[j].x, pa[j].y), pack2h(pa[j].z, pa[j].w));
            }
#pragma unroll
            for (int j = 0; j < 4; j++)
                *(uint2*)(sBn + (pr + 32 * j) * 40 + pc) =
                    make_uint2(pack2h(pb[j].x, pb[j].y), pack2h(pb[j].z, pb[j].w));
        }
        __syncthreads();
    }

#pragma unroll
    for (int mf = 0; mf < 2; mf++) {
        int r = m0 + wm * 32 + mf * 16 + g;
#pragma unroll
        for (int nf = 0; nf < 8; nf++) {
            int cc = n0 + wn * 64 + nf * 8 + t4 * 2;
            float v00 = acc[mf][nf][0] + bias[cc];
            float v01 = acc[mf][nf][1] + bias[cc + 1];
            float v10 = acc[mf][nf][2] + bias[cc];
            float v11 = acc[mf][nf][3] + bias[cc + 1];
            if (c_half) {
                __half* Ch = (__half*)Cout;
                *(__half2*)(Ch + (size_t)r * N + cc)       = __floats2half2_rn(v00, v01);
                *(__half2*)(Ch + (size_t)(r + 8) * N + cc) = __floats2half2_rn(v10, v11);
            } else {
                float* C = (float*)Cout;
                C[(size_t)r * N + cc]           = v00;
                C[(size_t)r * N + cc + 1]       = v01;
                C[(size_t)(r + 8) * N + cc]     = v10;
                C[(size_t)(r + 8) * N + cc + 1] = v11;
            }
        }
    }
}

// ============================================================================
// Transpose v (half in, half out): g_vprojh [b][s][h*64+d] -> g_vprojTh
// [bh][d][s]. Block = 64s x 64d tile of one (b,h). grid (SEQ/64, B*H).
// ============================================================================
__global__ __launch_bounds__(256) void transpose_v()
{
    __shared__ __half t[64][72];
    const int bh = blockIdx.y, b = bh >> 4, h = bh & 15;
    const int s0 = blockIdx.x * 64;
    const int r = threadIdx.x >> 2, c0 = (threadIdx.x & 3) * 16;

    const __half* src = g_vprojh + ((size_t)b * SEQ + s0 + r) * D_MODEL + h * DK + c0;
    *(uint4*)&t[r][c0]     = *(const uint4*)(src);
    *(uint4*)&t[r][c0 + 8] = *(const uint4*)(src + 8);
    __syncthreads();

    __half* dst = g_vprojTh + ((size_t)bh * DK + r) * SEQ + s0 + c0;
    unsigned q[8];
#pragma unroll
    for (int j = 0; j < 8; j++) {
        __half2 p = __halves2half2(t[c0 + 2 * j][r], t[c0 + 2 * j + 1][r]);
        q[j] = *(unsigned*)&p;
    }
    *(uint4*)(dst)     = make_uint4(q[0], q[1], q[2], q[3]);
    *(uint4*)(dst + 8) = make_uint4(q[4], q[5], q[6], q[7]);
}

// ============================================================================
// Fused softmax + attention mix, fp16 mma, coalesced W producer, fragment
// loads via ldmatrix (32 LDS.32 -> 8 LDSM per warp/chunk). Core pipeline
// identical to the verified 269us kernel.
// smem halves: P stages @0,@5120 (128x40); V stages @10240,@12800 (64x40);
// rowinv (float[128]) @15360h = byte 30720. Total 31232 B.
// ============================================================================
#define MIX_SMEM_REQ 31232

__global__ __launch_bounds__(256, 2) void mix_fp16(const float* __restrict__ W)
{
    extern __shared__ __half hsm[];
    float* rinv = (float*)(hsm + 15360);

    const int tid  = threadIdx.x;
    const int lane = tid & 31, warp = tid >> 5;
    const int g    = lane >> 2, t4 = lane & 3;
    const int wm = warp >> 1, wn = warp & 1;
    const int bh = blockIdx.y, b = bh >> 4, h = bh & 15;
    const int q0 = blockIdx.x * 128;

    // ldmatrix per-lane address components (bytes)
    const int lm_row = lane & 7;
    const unsigned aoff0 = (unsigned)(((wm * 32 + lm_row + ((lane >> 3) & 1) * 8) * 40
                                       + (lane >> 4) * 8) * 2);               // + mf*1280 + ks*2
    const unsigned boff0 = (unsigned)(((wn * 32 + (lane >> 4) * 8 + lm_row) * 40
                                       + ((lane >> 3) & 1) * 8) * 2);         // + pair*1280 + ks*2
    const unsigned sPb0 = smem_u32(hsm);
    const unsigned sVb0 = smem_u32(hsm + 10240);

    // W producer: thread t -> rows (t>>3)+32j, quarter-line (t&7)*4 floats
    const int prow = tid >> 3, pcol = (tid & 7) * 4;
    const float*    gWr[4];
    const unsigned* Mpr[4];
#pragma unroll
    for (int j = 0; j < 4; j++) {
        int row = prow + 32 * j;
        gWr[j] = W + ((size_t)bh * SEQ + q0 + row) * SEQ + pcol;
        Mpr[j] = g_maskbits + ((size_t)b * SEQ + q0 + row) * (SEQ / 32);
    }
    const unsigned psts = sPb0 + (unsigned)(prow * 40 + pcol) * 2;  // stage 0 base

    // V producer: thread t -> row t>>2 (d), granule t&3 (8 halves)
    const int vr = tid >> 2, vg = tid & 3;
    const __half* gV = g_vprojTh + (size_t)bh * DK * SEQ + (size_t)vr * SEQ + vg * 8;
    const unsigned sV0a = sVb0 + (unsigned)(vr * 40 + vg * 8) * 2;

    float acc[2][4][4];
#pragma unroll
    for (int i = 0; i < 2; i++)
#pragma unroll
        for (int j = 0; j < 4; j++)
#pragma unroll
            for (int k = 0; k < 4; k++) acc[i][j][k] = 0.f;

    float ls[4] = {0.f, 0.f, 0.f, 0.f};
    float4 w[4];
    unsigned mw[4];

    // ---- prologue: chunk 0 ----
#pragma unroll
    for (int j = 0; j < 4; j++) { w[j] = __ldcs((const float4*)(gWr[j])); mw[j] = Mpr[j][0]; }
    cp16s(sV0a, gV);                      // V chunk 0 -> stage 0
    CP_COMMIT();
    {   // produce P0 -> stage 0
#pragma unroll
        for (int j = 0; j < 4; j++) {
            float e0 = ((mw[j] >> (pcol + 0)) & 1u) ? __expf(w[j].x) : 0.f;
            float e1 = ((mw[j] >> (pcol + 1)) & 1u) ? __expf(w[j].y) : 0.f;
            float e2 = ((mw[j] >> (pcol + 2)) & 1u) ? __expf(w[j].z) : 0.f;
            float e3 = ((mw[j] >> (pcol + 3)) & 1u) ? __expf(w[j].w) : 0.f;
            ls[j] += (e0 + e1) + (e2 + e3);
            asm volatile("st.shared.v2.b32 [%0], {%1,%2};"
                :: "r"(psts + (unsigned)(j * 32 * 40) * 2),
                   "r"(pack2h(e0, e1)), "r"(pack2h(e2, e3)) : "memory");
        }
    }
#pragma unroll
    for (int j = 0; j < 4; j++) { w[j] = __ldcs((const float4*)(gWr[j] + 32)); mw[j] = Mpr[j][1]; }
    CP_WAIT0();
    __syncthreads();

    // ---- main loop ----
    for (int c = 0; c < 64; c++) {
        // V chunk c+1 -> stage (c+1)&1
        if (c + 1 < 64) {
            cp16s(sV0a + ((c + 1) & 1) * 5120, gV + (size_t)(c + 1) * 32);
            CP_COMMIT();
        }

        // mma on stage c&1 (ldmatrix fragments)
        {
            const unsigned sPc = sPb0 + (c & 1) * 10240;  // bytes
            const unsigned sVc = sVb0 + (c & 1) * 5120;
#pragma unroll
            for (int ks = 0; ks < 32; ks += 16) {
                unsigned a[2][4];
#pragma unroll
                for (int mf = 0; mf < 2; mf++)
                    ldsm4(a[mf][0], a[mf][1], a[mf][2], a[mf][3],
                          sPc + aoff0 + mf * 1280u + ks * 2u);
                unsigned bfr[4][2];
#pragma unroll
                for (int p = 0; p < 2; p++)
                    ldsm4(bfr[2 * p][0], bfr[2 * p][1], bfr[2 * p + 1][0], bfr[2 * p + 1][1],
                          sVc + boff0 + p * 1280u + ks * 2u);
#pragma unroll
                for (int nf = 0; nf < 4; nf++)
#pragma unroll
                    for (int mf = 0; mf < 2; mf++)
                        mma16(acc[mf][nf], a[mf], bfr[nf][0], bfr[nf][1]);
            }
        }

        // produce P(c+1) -> stage (c+1)&1 from regs w (= chunk c+1)
        if (c + 1 < 64) {
            const unsigned pb = psts + ((c + 1) & 1) * 10240;  // bytes
#pragma unroll
            for (int j = 0; j < 4; j++) {
                float e0 = ((mw[j] >> (pcol + 0)) & 1u) ? __expf(w[j].x) : 0.f;
                float e1 = ((mw[j] >> (pcol + 1)) & 1u) ? __expf(w[j].y) : 0.f;
                float e2 = ((mw[j] >> (pcol + 2)) & 1u) ? __expf(w[j].z) : 0.f;
                float e3 = ((mw[j] >> (pcol + 3)) & 1u) ? __expf(w[j].w) : 0.f;
                ls[j] += (e0 + e1) + (e2 + e3);
                asm volatile("st.shared.v2.b32 [%0], {%1,%2};"
                    :: "r"(pb + (unsigned)(j * 32 * 40) * 2),
                       "r"(pack2h(e0, e1)), "r"(pack2h(e2, e3)) : "memory");
            }
            // LDG W chunk c+2
            if (c + 2 < 64) {
#pragma unroll
                for (int j = 0; j < 4; j++) {
                    w[j] = __ldcs((const float4*)(gWr[j] + (size_t)(c + 2) * 32));
                    mw[j] = Mpr[j][c + 2];
                }
            }
            CP_WAIT0();
        }
        __syncthreads();
    }

    // row sums: 8 lanes per row -> shfl reduce, lane (t&7)==0 writes
#pragma unroll
    for (int j = 0; j < 4; j++) {
        float s = ls[j];
        s += __shfl_xor_sync(0xffffffffu, s, 1);
        s += __shfl_xor_sync(0xffffffffu, s, 2);
        s += __shfl_xor_sync(0xffffffffu, s, 4);
        if ((tid & 7) == 0) rinv[prow + 32 * j] = 1.0f / s;
    }
    __syncthreads();

    // epilogue: scale by 1/rowsum, write x as half [b, q, h*64 + d]
    {
        __half* Xb = g_xh + (size_t)b * SEQ * D_MODEL + h * DK;
#pragma unroll
        for (int mf = 0; mf < 2; mf++) {
            int rr = wm * 32 + mf * 16 + g;
            float s0 = rinv[rr];
            float s1 = rinv[rr + 8];
            int qr = q0 + rr;
#pragma unroll
            for (int nf = 0; nf < 4; nf++) {
                int n = wn * 32 + nf * 8 + t4 * 2;
                *(__half2*)(Xb + (size_t)qr * D_MODEL + n) =
                    __floats2half2_rn(acc[mf][nf][0] * s0, acc[mf][nf][1] * s0);
                *(__half2*)(Xb + (size_t)(qr + 8) * D_MODEL + n) =
                    __floats2half2_rn(acc[mf][nf][2] * s1, acc[mf][nf][3] * s1);
            }
        }
    }
}

// ============================================================================
// Launch: pack mask -> V-proj GEMM (fp32 A, half C) -> transpose(half) ->
//         mix (half x out) -> O-proj GEMM (half A, fp32 C)
// Inputs: 0 query(unused) 1 key(unused) 2 value 3 weight 4 mask(int32)
//         5 V_w 6 V_b 7 O_w 8 O_b
// ============================================================================
extern "C" void kernel_launch(void* const* d_in, const int* in_sizes, int n_in,
                              void* d_out, int out_size)
{
    const float* value  = (const float*)d_in[2];
    const float* weight = (const float*)d_in[3];
    const int*   mask   = (const int*)d_in[4];
    const float* V_w    = (const float*)d_in[5];
    const float* V_b    = (const float*)d_in[6];
    const float* O_w    = (const float*)d_in[7];
    const float* O_b    = (const float*)d_in[8];
    float* out          = (float*)d_out;

    __half *vph, *xph;
    unsigned* mb;
    cudaGetSymbolAddress((void**)&vph, g_vprojh);
    cudaGetSymbolAddress((void**)&xph, g_xh);
    cudaGetSymbolAddress((void**)&mb, g_maskbits);

    cudaFuncSetAttribute(gemm_fp16, cudaFuncAttributeMaxDynamicSharedMemorySize, 40960);
    cudaFuncSetAttribute(mix_fp16, cudaFuncAttributeMaxDynamicSharedMemorySize, MIX_SMEM_REQ);

    const int n_words = BATCH * SEQ * (SEQ / 32);

    dim3 blk(256);
    dim3 g0((n_words + 7) / 8);
    dim3 g1(D_MODEL / 128, (BATCH * SEQ) / 128);   // (8, 64)
    dim3 gt(SEQ / 64, BATCH * NH);                 // (32, 64)
    dim3 g2(SEQ / 128, BATCH * NH);                // (16, 64)

    pack_mask<<<g0, blk>>>(mask, mb, n_words);
    gemm_fp16<<<g1, blk, 40960>>>(value, 0, V_w, V_b, vph, 1, BATCH * SEQ, D_MODEL, D_MODEL);
    transpose_v<<<gt, blk>>>();
    mix_fp16<<<g2, blk, MIX_SMEM_REQ>>>(weight);
    gemm_fp16<<<g1, blk, 40960>>>(xph, 1, O_w, O_b, out, 0, BATCH * SEQ, D_MODEL, D_MODEL);
}